// round 12
// baseline (speedup 1.0000x reference)
#include <cuda_runtime.h>
#include <cuda_fp16.h>
#include <cstdint>
#include <math.h>

#define TOKS 512
#define HDIM 1024
#define FDIM 4096
#define NEXP 8
#define SLOT 512
#define KSPLIT 4
#define RS 40                         // halves per A smem row (80 B)
#define SSTF 36                       // floats per B smem row (144 B)

// gemm1 smem map (bytes): A ring-3 fp16 64x32h, B ring-3 fp32 128x32f (w1|w3)
#define G1_AST 5120
#define G1_BST 18432
#define G1_A   0
#define G1_B   15360
#define G1_CTL 70656                  // fullA[3]@0,emptyA[3]@24,fullB[3]@48,emptyB[3]@72
#define G1_SM  (G1_CTL + 96)
// gemm2: A ring-3 fp16 128x32h, B ring-3 fp32 64x32f
#define G2_AST 10240
#define G2_BST 9216
#define G2_A   0
#define G2_B   30720
#define G2_CTL 58368
#define G2_SM  (G2_CTL + 96)

__device__ __half d_xh[TOKS * HDIM];
__device__ __half d_h[NEXP * SLOT * FDIM];
__device__ float  d_po[KSPLIT * NEXP * SLOT * HDIM];
__device__ int    d_count[NEXP];
__device__ int    d_tok[NEXP * SLOT];
__device__ float  d_mult[NEXP * SLOT];
__device__ int    d_pidx[TOKS * 2];

// ---------------- helpers ----------------------------------------------------
__device__ __forceinline__ unsigned pk2(float a, float b) {
    __half2 h = __floats2half2_rn(a, b); return *(unsigned*)&h;
}
__device__ __forceinline__ void mma16(float* c, const unsigned* a, const unsigned* b) {
    asm volatile("mma.sync.aligned.m16n8k16.row.col.f32.f16.f16.f32 "
        "{%0,%1,%2,%3}, {%4,%5,%6,%7}, {%8,%9}, {%0,%1,%2,%3};"
        : "+f"(c[0]), "+f"(c[1]), "+f"(c[2]), "+f"(c[3])
        : "r"(a[0]), "r"(a[1]), "r"(a[2]), "r"(a[3]), "r"(b[0]), "r"(b[1]));
}
__device__ __forceinline__ void ldsm4(unsigned* r, unsigned addr) {
    asm volatile("ldmatrix.sync.aligned.m8n8.x4.shared.b16 {%0,%1,%2,%3}, [%4];"
        : "=r"(r[0]), "=r"(r[1]), "=r"(r[2]), "=r"(r[3]) : "r"(addr));
}
__device__ __forceinline__ void bfrag(const float* rowp, unsigned* br) {
    float2 lo = *(const float2*)rowp; float2 hi = *(const float2*)(rowp + 8);
    br[0] = pk2(lo.x, lo.y); br[1] = pk2(hi.x, hi.y);
}
__device__ __forceinline__ void cpa(unsigned dst, const void* src) {
    asm volatile("cp.async.cg.shared.global [%0], [%1], 16;" :: "r"(dst), "l"(src));
}
#define CP_COMMIT asm volatile("cp.async.commit_group;")
#define CP_WAIT0  asm volatile("cp.async.wait_group 0;")
#define MBAR_INIT(m, c)  asm volatile("mbarrier.init.shared.b64 [%0], %1;" :: "r"(m), "r"(c) : "memory")
#define MBAR_ARRIVE(m)   asm volatile("mbarrier.arrive.shared.b64 _, [%0];" :: "r"(m) : "memory")
#define MBAR_WAIT(m, ph) asm volatile("{\n\t.reg .pred P1;\n\tWL%=:\n\t" \
    "mbarrier.try_wait.parity.acquire.cta.shared::cta.b64 P1, [%0], %1, 0x989680;\n\t" \
    "@P1 bra.uni WD%=;\n\tbra.uni WL%=;\n\tWD%=:\n\t}" \
    :: "r"((unsigned)(m)), "r"((unsigned)(ph)) : "memory")

// ---------------- small kernels ----------------------------------------------
__global__ void convx_kernel(const float* __restrict__ x) {
    if (blockIdx.x == 0 && threadIdx.x < NEXP) d_count[threadIdx.x] = 0;
    int i = (blockIdx.x * 256 + threadIdx.x) * 4;
    float4 v = *(const float4*)(x + i);
    uint2 o; o.x = pk2(v.x, v.y); o.y = pk2(v.z, v.w);
    *(uint2*)&d_xh[i] = o;
}
__global__ void routing_kernel(const float* __restrict__ x, const float* __restrict__ gw) {
    int t = blockIdx.x, tid = threadIdx.x, w = tid >> 5, lane = tid & 31;
    __shared__ float lg[NEXP];
    const float* xr = x + (size_t)t * HDIM;
    const float* gr = gw + (size_t)w * HDIM;
    float s = 0.f;
    for (int i = lane * 4; i < HDIM; i += 128) {
        float4 a = *(const float4*)(xr + i);
        float4 b = *(const float4*)(gr + i);
        s += a.x * b.x + a.y * b.y + a.z * b.z + a.w * b.w;
    }
    #pragma unroll
    for (int o = 16; o; o >>= 1) s += __shfl_xor_sync(0xFFFFFFFFu, s, o);
    if (lane == 0) lg[w] = s;
    __syncthreads();
    if (tid == 0) {
        float l[NEXP];
        #pragma unroll
        for (int e = 0; e < NEXP; e++) l[e] = lg[e];
        int s1 = 0;
        for (int e = 1; e < NEXP; e++) if (l[e] > l[s1]) s1 = e;
        float m1 = l[s1];
        int s2 = (s1 == 0) ? 1 : 0;
        for (int e = 0; e < NEXP; e++) { if (e == s1) continue; if (l[e] > l[s2]) s2 = e; }
        float m2 = l[s2];
        float mult1, mult2;
        {
            float keep[NEXP]; float mx = -1e30f;
            for (int e = 0; e < NEXP; e++) {
                float f = fmaxf(fabsf(l[e]), m1);
                keep[e] = ((m1 - l[e]) / f > 0.02f) ? -1e30f : l[e];
                mx = fmaxf(mx, keep[e]);
            }
            float sum = 0.f, num = 0.f;
            for (int e = 0; e < NEXP; e++) {
                float p = (keep[e] <= -1e30f) ? 0.f : expf(keep[e] - mx);
                sum += p; if (e == s1) num = p;
            }
            mult1 = num / sum;
        }
        {
            float keep[NEXP]; float mx = -1e30f;
            for (int e = 0; e < NEXP; e++) {
                float f = fmaxf(fabsf(l[e]), m2);
                bool msk = ((m2 - l[e]) / f > 0.02f) || (e == s1);
                keep[e] = msk ? -1e30f : l[e];
                mx = fmaxf(mx, keep[e]);
            }
            float sum = 0.f, num = 0.f;
            for (int e = 0; e < NEXP; e++) {
                float p = (keep[e] <= -1e30f) ? 0.f : expf(keep[e] - mx);
                sum += p; if (e == s2) num = p;
            }
            mult2 = num / sum;
        }
        int p = atomicAdd(&d_count[s1], 1);
        d_tok[s1 * SLOT + p] = t; d_mult[s1 * SLOT + p] = mult1;
        d_pidx[t * 2 + 0] = s1 * SLOT + p;
        p = atomicAdd(&d_count[s2], 1);
        d_tok[s2 * SLOT + p] = t; d_mult[s2 * SLOT + p] = mult2;
        d_pidx[t * 2 + 1] = s2 * SLOT + p;
    }
}

// ---------------- GEMM1: warp-specialized, 64x64 fused w1/w3 -----------------
__global__ __launch_bounds__(320, 3) void gemm1_kernel(const float* __restrict__ w1,
                                                       const float* __restrict__ w3) {
    extern __shared__ char smem[];
    int e = blockIdx.y >> 3, mtile = blockIdx.y & 7;
    int cnt = d_count[e];
    int m0 = mtile * 64;
    if (m0 >= cnt) return;
    int n0 = blockIdx.x * 64;
    unsigned sb = (unsigned)__cvta_generic_to_shared(smem);
    int tid = threadIdx.x, wid = tid >> 5, lane = tid & 31;
    const int NKT = HDIM / 32;   // 32

    if (tid == 0) {
        #pragma unroll
        for (int i = 0; i < 3; i++) {
            MBAR_INIT(sb + G1_CTL + i * 8, 32);        // fullA
            MBAR_INIT(sb + G1_CTL + 24 + i * 8, 8);    // emptyA
            MBAR_INIT(sb + G1_CTL + 48 + i * 8, 32);   // fullB
            MBAR_INIT(sb + G1_CTL + 72 + i * 8, 8);    // emptyB
        }
    }
    __syncthreads();

    if (wid == 8) {          // ---- A producer: rows 2*lane, 2*lane+1 ----
        const __half* src[2];
        #pragma unroll
        for (int j = 0; j < 2; j++) {
            int row = 2 * lane + j;
            int rr = m0 + row; if (rr >= cnt) rr = cnt - 1;
            src[j] = d_xh + (size_t)d_tok[e * SLOT + rr] * HDIM;
        }
        for (int s = 0; s < NKT; s++) {
            MBAR_WAIT(sb + G1_CTL + 24 + (s % 3) * 8, ((s / 3) & 1) ^ 1);
            unsigned dsl = sb + G1_A + (unsigned)(s % 3) * G1_AST;
            #pragma unroll
            for (int j = 0; j < 2; j++)
                #pragma unroll
                for (int c = 0; c < 4; c++)
                    cpa(dsl + (unsigned)(2 * lane + j) * 80 + c * 16, src[j] + s * 32 + c * 8);
            CP_COMMIT; CP_WAIT0;
            MBAR_ARRIVE(sb + G1_CTL + (s % 3) * 8);
        }
        return;
    }
    if (wid == 9) {          // ---- B producer: rows 4*lane..+3 (w1|w3) ----
        const float* src[4];
        #pragma unroll
        for (int j = 0; j < 4; j++) {
            int row = 4 * lane + j;
            src[j] = (row < 64)
                ? w1 + ((size_t)e * FDIM + n0 + row) * HDIM
                : w3 + ((size_t)e * FDIM + n0 + row - 64) * HDIM;
        }
        for (int s = 0; s < NKT; s++) {
            MBAR_WAIT(sb + G1_CTL + 72 + (s % 3) * 8, ((s / 3) & 1) ^ 1);
            unsigned dsl = sb + G1_B + (unsigned)(s % 3) * G1_BST;
            #pragma unroll
            for (int j = 0; j < 4; j++)
                #pragma unroll
                for (int c = 0; c < 8; c++)
                    cpa(dsl + (unsigned)(4 * lane + j) * 144 + c * 16, src[j] + s * 32 + c * 4);
            CP_COMMIT; CP_WAIT0;
            MBAR_ARRIVE(sb + G1_CTL + 48 + (s % 3) * 8);
        }
        return;
    }

    // ---- consumers: 8 warps, 2x4 grid, warp tile 32x16 (per matrix) ----
    int wm = wid >> 2, wn = wid & 3;
    int g = lane >> 2, tg = lane & 3;
    int bq = lane & 3, bn = lane >> 2;
    unsigned aoffm[2];
    #pragma unroll
    for (int mi = 0; mi < 2; mi++)
        aoffm[mi] = (unsigned)((wm * 32 + mi * 16 + (lane & 7) + ((lane >> 3) & 1) * 8) * RS
                               + (lane >> 4) * 8) * 2;

    float acc1[2][2][4] = {}, acc3[2][2][4] = {};

    for (int kt = 0; kt < NKT; kt++) {
        int slot = kt % 3, ph = (kt / 3) & 1;
        MBAR_WAIT(sb + G1_CTL + slot * 8, ph);
        MBAR_WAIT(sb + G1_CTL + 48 + slot * 8, ph);

        unsigned sAc = sb + G1_A + (unsigned)slot * G1_AST;
        const float* Bc = (const float*)(smem + G1_B + slot * G1_BST);

        #pragma unroll
        for (int ks = 0; ks < 2; ks++) {
            unsigned af[2][4];
            ldsm4(af[0], sAc + aoffm[0] + ks * 32);
            ldsm4(af[1], sAc + aoffm[1] + ks * 32);
            int k0 = ks * 16 + 2 * bq;
            #pragma unroll
            for (int ni = 0; ni < 2; ni++) {
                int rowb = (wn * 16 + ni * 8 + bn) * SSTF + k0;
                unsigned br1[2], br3[2];
                bfrag(Bc + rowb, br1);
                bfrag(Bc + rowb + 64 * SSTF, br3);
                #pragma unroll
                for (int mi = 0; mi < 2; mi++) {
                    mma16(acc1[mi][ni], af[mi], br1);
                    mma16(acc3[mi][ni], af[mi], br3);
                }
            }
        }
        __syncwarp();
        if (lane == 0) {
            MBAR_ARRIVE(sb + G1_CTL + 24 + slot * 8);
            MBAR_ARRIVE(sb + G1_CTL + 72 + slot * 8);
        }
    }

    #pragma unroll
    for (int mi = 0; mi < 2; mi++)
    #pragma unroll
    for (int ni = 0; ni < 2; ni++)
    #pragma unroll
    for (int h = 0; h < 2; h++) {
        int lr = wm * 32 + mi * 16 + g + h * 8;
        if (m0 + lr < cnt) {
            int col = n0 + wn * 16 + ni * 8 + tg * 2;
            float v1a = acc1[mi][ni][h * 2], v1b = acc1[mi][ni][h * 2 + 1];
            float v3a = acc3[mi][ni][h * 2], v3b = acc3[mi][ni][h * 2 + 1];
            float h0 = v1a * v3a / (1.f + __expf(-v1a));
            float h1 = v1b * v3b / (1.f + __expf(-v1b));
            *(unsigned*)&d_h[((size_t)(e * SLOT + m0 + lr)) * FDIM + col] = pk2(h0, h1);
        }
    }
}

// ---------------- GEMM2: warp-specialized, 128x64, split-K x4 ----------------
__global__ __launch_bounds__(320, 3) void gemm2_kernel(const float* __restrict__ w2) {
    extern __shared__ char smem[];
    int e = blockIdx.y >> 2, mtile = blockIdx.y & 3;
    int cnt = d_count[e];
    int m0 = mtile * 128;
    if (m0 >= cnt) return;
    int n0 = blockIdx.x * 64;
    int kz = blockIdx.z;
    int kbase = kz * (FDIM / KSPLIT);
    unsigned sb = (unsigned)__cvta_generic_to_shared(smem);
    int tid = threadIdx.x, wid = tid >> 5, lane = tid & 31;
    const int NKT = (FDIM / KSPLIT) / 32;   // 32

    if (tid == 0) {
        #pragma unroll
        for (int i = 0; i < 3; i++) {
            MBAR_INIT(sb + G2_CTL + i * 8, 32);
            MBAR_INIT(sb + G2_CTL + 24 + i * 8, 8);
            MBAR_INIT(sb + G2_CTL + 48 + i * 8, 32);
            MBAR_INIT(sb + G2_CTL + 72 + i * 8, 8);
        }
    }
    __syncthreads();

    if (wid == 8) {          // ---- A producer: 128 rows of d_h, 4/lane ----
        const __half* src[4];
        #pragma unroll
        for (int j = 0; j < 4; j++) {
            int row = 4 * lane + j;
            int rr = m0 + row; if (rr >= cnt) rr = cnt - 1;
            src[j] = d_h + ((size_t)(e * SLOT) + rr) * FDIM + kbase;
        }
        for (int s = 0; s < NKT; s++) {
            MBAR_WAIT(sb + G2_CTL + 24 + (s % 3) * 8, ((s / 3) & 1) ^ 1);
            unsigned dsl = sb + G2_A + (unsigned)(s % 3) * G2_AST;
            #pragma unroll
            for (int j = 0; j < 4; j++)
                #pragma unroll
                for (int c = 0; c < 4; c++)
                    cpa(dsl + (unsigned)(4 * lane + j) * 80 + c * 16, src[j] + s * 32 + c * 8);
            CP_COMMIT; CP_WAIT0;
            MBAR_ARRIVE(sb + G2_CTL + (s % 3) * 8);
        }
        return;
    }
    if (wid == 9) {          // ---- B producer: 64 rows of w2, 2/lane ----
        const float* src[2];
        #pragma unroll
        for (int j = 0; j < 2; j++) {
            int row = 2 * lane + j;
            src[j] = w2 + ((size_t)e * HDIM + n0 + row) * FDIM + kbase;
        }
        for (int s = 0; s < NKT; s++) {
            MBAR_WAIT(sb + G2_CTL + 72 + (s % 3) * 8, ((s / 3) & 1) ^ 1);
            unsigned dsl = sb + G2_B + (unsigned)(s % 3) * G2_BST;
            #pragma unroll
            for (int j = 0; j < 2; j++)
                #pragma unroll
                for (int c = 0; c < 8; c++)
                    cpa(dsl + (unsigned)(2 * lane + j) * 144 + c * 16, src[j] + s * 32 + c * 4);
            CP_COMMIT; CP_WAIT0;
            MBAR_ARRIVE(sb + G2_CTL + 48 + (s % 3) * 8);
        }
        return;
    }

    // ---- consumers: 8 warps, 4x2 grid, warp tile 32x32 ----
    int wm = wid >> 1, wn = wid & 1;
    int g = lane >> 2, tg = lane & 3;
    int bq = lane & 3, bn = lane >> 2;
    unsigned aoffm[2];
    #pragma unroll
    for (int mi = 0; mi < 2; mi++)
        aoffm[mi] = (unsigned)((wm * 32 + mi * 16 + (lane & 7) + ((lane >> 3) & 1) * 8) * RS
                               + (lane >> 4) * 8) * 2;

    float acc[2][4][4] = {};

    for (int kt = 0; kt < NKT; kt++) {
        int slot = kt % 3, ph = (kt / 3) & 1;
        MBAR_WAIT(sb + G2_CTL + slot * 8, ph);
        MBAR_WAIT(sb + G2_CTL + 48 + slot * 8, ph);

        unsigned sAc = sb + G2_A + (unsigned)slot * G2_AST;
        const float* Bc = (const float*)(smem + G2_B + slot * G2_BST);

        #pragma unroll
        for (int ks = 0; ks < 2; ks++) {
            unsigned af[2][4];
            ldsm4(af[0], sAc + aoffm[0] + ks * 32);
            ldsm4(af[1], sAc + aoffm[1] + ks * 32);
            int k0 = ks * 16 + 2 * bq;
            #pragma unroll
            for (int ni = 0; ni < 4; ni++) {
                int rowb = (wn * 32 + ni * 8 + bn) * SSTF + k0;
                unsigned br[2];
                bfrag(Bc + rowb, br);
                #pragma unroll
                for (int mi = 0; mi < 2; mi++) mma16(acc[mi][ni], af[mi], br);
            }
        }
        __syncwarp();
        if (lane == 0) {
            MBAR_ARRIVE(sb + G2_CTL + 24 + slot * 8);
            MBAR_ARRIVE(sb + G2_CTL + 72 + slot * 8);
        }
    }

    float* po = d_po + (size_t)kz * (NEXP * SLOT * HDIM);
    #pragma unroll
    for (int mi = 0; mi < 2; mi++)
    #pragma unroll
    for (int ni = 0; ni < 4; ni++)
    #pragma unroll
    for (int h = 0; h < 2; h++) {
        int lr = wm * 32 + mi * 16 + g + h * 8;
        if (m0 + lr < cnt) {
            float mult = d_mult[e * SLOT + m0 + lr];
            int col = n0 + wn * 32 + ni * 8 + tg * 2;
            float2 o;
            o.x = acc[mi][ni][h * 2]     * mult;
            o.y = acc[mi][ni][h * 2 + 1] * mult;
            *(float2*)&po[((size_t)(e * SLOT + m0 + lr)) * HDIM + col] = o;
        }
    }
}

// ---------------- finalize ---------------------------------------------------
__global__ void finalize_kernel(float* __restrict__ out) {
    int t = blockIdx.x, i = threadIdx.x;
    int p0 = d_pidx[t * 2], p1 = d_pidx[t * 2 + 1];
    float4 o = make_float4(0.f, 0.f, 0.f, 0.f);
    #pragma unroll
    for (int kz = 0; kz < KSPLIT; kz++) {
        const float* po = d_po + (size_t)kz * (NEXP * SLOT * HDIM);
        float4 a = ((const float4*)(po + (size_t)p0 * HDIM))[i];
        float4 b = ((const float4*)(po + (size_t)p1 * HDIM))[i];
        o.x += a.x + b.x; o.y += a.y + b.y;
        o.z += a.z + b.z; o.w += a.w + b.w;
    }
    ((float4*)(out + (size_t)t * HDIM))[i] = o;
}

// ---------------- launch ----------------------------------------------------
extern "C" void kernel_launch(void* const* d_in, const int* in_sizes, int n_in,
                              void* d_out, int out_size) {
    const float* x  = (const float*)d_in[0];
    const float* gw = (const float*)d_in[1];
    const float* w1 = (const float*)d_in[2];
    const float* w2 = (const float*)d_in[3];
    const float* w3 = (const float*)d_in[4];
    float* out = (float*)d_out;

    cudaFuncSetAttribute(gemm1_kernel, cudaFuncAttributeMaxDynamicSharedMemorySize, G1_SM);
    cudaFuncSetAttribute(gemm2_kernel, cudaFuncAttributeMaxDynamicSharedMemorySize, G2_SM);

    convx_kernel<<<TOKS * HDIM / 1024, 256>>>(x);
    routing_kernel<<<TOKS, 256>>>(x, gw);
    gemm1_kernel<<<dim3(FDIM / 64, NEXP * 8), 320, G1_SM>>>(w1, w3);
    gemm2_kernel<<<dim3(HDIM / 64, NEXP * 4, KSPLIT), 320, G2_SM>>>(w2);
    finalize_kernel<<<TOKS, 256>>>(out);
}

// round 13
// speedup vs baseline: 1.3942x; 1.3942x over previous
#include <cuda_runtime.h>
#include <cuda_fp16.h>
#include <cstdint>
#include <math.h>

#define TOKS 512
#define HDIM 1024
#define FDIM 4096
#define NEXP 8
#define SLOT 512
#define SSTH 40                    // halves per smem row (80 B, ldsm conflict-free)
#define ROWH64  (64 * SSTH)        // 2560 halves per 64-row stage
#define ROWH128 (128 * SSTH)       // 5120 halves per 128-row stage

// ---------------- scratch (static device globals) ---------------------------
__device__ __half d_xh[TOKS * HDIM];               // fp16 x (1 MB)
__device__ __half d_h[NEXP * SLOT * FDIM];         // fp16 intermediate h (32 MB)
__device__ float  d_po2[2 * NEXP * SLOT * HDIM];   // split-K partials (fp32)
__device__ int    d_count[NEXP];
__device__ int    d_tok[NEXP * SLOT];
__device__ float  d_mult[NEXP * SLOT];
__device__ int    d_pidx[TOKS * 2];

// ---------------- helpers ----------------------------------------------------
__device__ __forceinline__ unsigned pk2(float a, float b) {
    __half2 h = __floats2half2_rn(a, b);
    return *(unsigned*)&h;
}
__device__ __forceinline__ void mma16(float* c, const unsigned* a, const unsigned* b) {
    asm volatile(
        "mma.sync.aligned.m16n8k16.row.col.f32.f16.f16.f32 "
        "{%0,%1,%2,%3}, {%4,%5,%6,%7}, {%8,%9}, {%0,%1,%2,%3};"
        : "+f"(c[0]), "+f"(c[1]), "+f"(c[2]), "+f"(c[3])
        : "r"(a[0]), "r"(a[1]), "r"(a[2]), "r"(a[3]), "r"(b[0]), "r"(b[1]));
}
__device__ __forceinline__ void ldsm4(unsigned* r, unsigned addr) {
    asm volatile("ldmatrix.sync.aligned.m8n8.x4.shared.b16 {%0,%1,%2,%3}, [%4];"
        : "=r"(r[0]), "=r"(r[1]), "=r"(r[2]), "=r"(r[3]) : "r"(addr));
}
__device__ __forceinline__ void cpa(unsigned dst, const void* src) {
    asm volatile("cp.async.cg.shared.global [%0], [%1], 16;" :: "r"(dst), "l"(src));
}
#define CP_COMMIT asm volatile("cp.async.commit_group;")
#define CP_WAIT2  asm volatile("cp.async.wait_group 2;")

// ---------------- init / convx ----------------------------------------------
__global__ void init_kernel() {
    if (threadIdx.x < NEXP) d_count[threadIdx.x] = 0;
}
__global__ void convx_kernel(const float* __restrict__ x) {
    int i = (blockIdx.x * 256 + threadIdx.x) * 4;
    float4 v = *(const float4*)(x + i);
    uint2 o; o.x = pk2(v.x, v.y); o.y = pk2(v.z, v.w);
    *(uint2*)&d_xh[i] = o;
}

// ---------------- routing ---------------------------------------------------
__global__ void routing_kernel(const float* __restrict__ x,
                               const float* __restrict__ gw) {
    int t = blockIdx.x;
    int tid = threadIdx.x;
    int w = tid >> 5, lane = tid & 31;
    __shared__ float lg[NEXP];

    const float* xr = x + (size_t)t * HDIM;
    const float* gr = gw + (size_t)w * HDIM;
    float s = 0.f;
    for (int i = lane * 4; i < HDIM; i += 128) {
        float4 a = *(const float4*)(xr + i);
        float4 b = *(const float4*)(gr + i);
        s += a.x * b.x + a.y * b.y + a.z * b.z + a.w * b.w;
    }
    #pragma unroll
    for (int o = 16; o; o >>= 1) s += __shfl_xor_sync(0xFFFFFFFFu, s, o);
    if (lane == 0) lg[w] = s;
    __syncthreads();

    if (tid == 0) {
        float l[NEXP];
        #pragma unroll
        for (int e = 0; e < NEXP; e++) l[e] = lg[e];

        int s1 = 0;
        for (int e = 1; e < NEXP; e++) if (l[e] > l[s1]) s1 = e;
        float m1 = l[s1];
        int s2 = (s1 == 0) ? 1 : 0;
        for (int e = 0; e < NEXP; e++) { if (e == s1) continue; if (l[e] > l[s2]) s2 = e; }
        float m2 = l[s2];

        float mult1, mult2;
        {
            float keep[NEXP]; float mx = -1e30f;
            for (int e = 0; e < NEXP; e++) {
                float f = fmaxf(fabsf(l[e]), m1);
                keep[e] = ((m1 - l[e]) / f > 0.02f) ? -1e30f : l[e];
                mx = fmaxf(mx, keep[e]);
            }
            float sum = 0.f, num = 0.f;
            for (int e = 0; e < NEXP; e++) {
                float p = (keep[e] <= -1e30f) ? 0.f : expf(keep[e] - mx);
                sum += p; if (e == s1) num = p;
            }
            mult1 = num / sum;
        }
        {
            float keep[NEXP]; float mx = -1e30f;
            for (int e = 0; e < NEXP; e++) {
                float f = fmaxf(fabsf(l[e]), m2);
                bool msk = ((m2 - l[e]) / f > 0.02f) || (e == s1);
                keep[e] = msk ? -1e30f : l[e];
                mx = fmaxf(mx, keep[e]);
            }
            float sum = 0.f, num = 0.f;
            for (int e = 0; e < NEXP; e++) {
                float p = (keep[e] <= -1e30f) ? 0.f : expf(keep[e] - mx);
                sum += p; if (e == s2) num = p;
            }
            mult2 = num / sum;
        }

        int p = atomicAdd(&d_count[s1], 1);
        d_tok[s1 * SLOT + p] = t; d_mult[s1 * SLOT + p] = mult1;
        d_pidx[t * 2 + 0] = s1 * SLOT + p;
        p = atomicAdd(&d_count[s2], 1);
        d_tok[s2 * SLOT + p] = t; d_mult[s2 * SLOT + p] = mult2;
        d_pidx[t * 2 + 1] = s2 * SLOT + p;
    }
}

// ---------------- GEMM1: 64x64 tile, fused w1/w3, fp16 mma ------------------
// smem: A ring-4 (fp16, cp.async from d_xh) + B1/B3 double buf (LDG fp32 -> cvt)
__global__ __launch_bounds__(256, 4) void gemm1_kernel(const float* __restrict__ w1,
                                                       const float* __restrict__ w3) {
    extern __shared__ __half smh[];
    __half* Ab  = smh;                       // 4 * ROWH64
    __half* B1b = smh + 4 * ROWH64;          // 2 * ROWH64
    __half* B3b = smh + 6 * ROWH64;          // 2 * ROWH64

    int e = blockIdx.y >> 3, mtile = blockIdx.y & 7;
    int cnt = d_count[e];
    int m0 = mtile * 64;
    if (m0 >= cnt) return;
    int n0 = blockIdx.x * 64;

    int tid = threadIdx.x;
    // A cp.async: thread -> (row = tid>>2, 16B chunk = tid&3)
    int arow = tid >> 2, ac = tid & 3;
    int rr = m0 + arow; if (rr >= cnt) rr = cnt - 1;
    const __half* aptr = d_xh + (size_t)d_tok[e * SLOT + rr] * HDIM + ac * 8;
    unsigned aoffs = (unsigned)(arow * SSTH + ac * 8) * 2;

    // B LDG: thread -> (row = tid>>2, 8 floats at (tid&3)*8)
    const float* b1p = w1 + ((size_t)e * FDIM + n0 + arow) * HDIM + ac * 8;
    const float* b3p = w3 + ((size_t)e * FDIM + n0 + arow) * HDIM + ac * 8;
    unsigned bsts = (unsigned)(arow * SSTH + ac * 8) * 2;

    unsigned uA  = (unsigned)__cvta_generic_to_shared(Ab);
    unsigned uB1 = (unsigned)__cvta_generic_to_shared(B1b);
    unsigned uB3 = (unsigned)__cvta_generic_to_shared(B3b);

    const int NKT = HDIM / 32;  // 32

    // prologue: B regs for kt=0; A stages 0,1,2
    float4 pb1a = *(const float4*)b1p, pb1b = *(const float4*)(b1p + 4);
    float4 pb3a = *(const float4*)b3p, pb3b = *(const float4*)(b3p + 4);
    #pragma unroll
    for (int s = 0; s < 3; s++) {
        cpa(uA + (unsigned)s * (ROWH64 * 2) + aoffs, aptr + s * 32);
        CP_COMMIT;
    }

    int warp = tid >> 5, lane = tid & 31;
    int wm = warp >> 2, wn = warp & 3;     // 2 x 4 warps, warp tile 32x16
    int g = lane >> 2, tg = lane & 3;

    // ldsm offsets (bytes, relative to stage base)
    unsigned aoffm[2], boff;
    #pragma unroll
    for (int mi = 0; mi < 2; mi++)
        aoffm[mi] = (unsigned)((wm * 32 + mi * 16 + (lane & 7) + ((lane >> 3) & 1) * 8) * SSTH
                               + (lane >> 4) * 8) * 2;
    boff = (unsigned)((wn * 16 + (lane & 7) + ((lane >> 4) & 1) * 8) * SSTH
                      + ((lane >> 3) & 1) * 8) * 2;

    float acc1[2][2][4] = {}, acc3[2][2][4] = {};

    for (int kt = 0; kt < NKT; kt++) {
        // convert+store this k-tile's weights (regs loaded one tile ago)
        { uint4 u; u.x = pk2(pb1a.x, pb1a.y); u.y = pk2(pb1a.z, pb1a.w);
          u.z = pk2(pb1b.x, pb1b.y); u.w = pk2(pb1b.z, pb1b.w);
          *(uint4*)((char*)B1b + ((kt & 1) * (ROWH64 * 2) + bsts)) = u; }
        { uint4 u; u.x = pk2(pb3a.x, pb3a.y); u.y = pk2(pb3a.z, pb3a.w);
          u.z = pk2(pb3b.x, pb3b.y); u.w = pk2(pb3b.z, pb3b.w);
          *(uint4*)((char*)B3b + ((kt & 1) * (ROWH64 * 2) + bsts)) = u; }
        CP_WAIT2;
        __syncthreads();

        if (kt + 1 < NKT) {
            const float* p1 = b1p + (kt + 1) * 32;
            const float* p3 = b3p + (kt + 1) * 32;
            pb1a = *(const float4*)p1; pb1b = *(const float4*)(p1 + 4);
            pb3a = *(const float4*)p3; pb3b = *(const float4*)(p3 + 4);
        }
        if (kt + 3 < NKT)
            cpa(uA + (unsigned)((kt + 3) & 3) * (ROWH64 * 2) + aoffs, aptr + (kt + 3) * 32);
        CP_COMMIT;

        unsigned sAc  = uA  + (unsigned)(kt & 3) * (ROWH64 * 2);
        unsigned sB1c = uB1 + (unsigned)(kt & 1) * (ROWH64 * 2);
        unsigned sB3c = uB3 + (unsigned)(kt & 1) * (ROWH64 * 2);

        #pragma unroll
        for (int ks = 0; ks < 2; ks++) {
            unsigned kb = (unsigned)ks * 32;   // 16 halves
            unsigned af[2][4], b1r[4], b3r[4];
            ldsm4(af[0], sAc + aoffm[0] + kb);
            ldsm4(af[1], sAc + aoffm[1] + kb);
            ldsm4(b1r, sB1c + boff + kb);
            ldsm4(b3r, sB3c + boff + kb);
            #pragma unroll
            for (int ni = 0; ni < 2; ni++)
            #pragma unroll
            for (int mi = 0; mi < 2; mi++) {
                mma16(acc1[mi][ni], af[mi], &b1r[ni * 2]);
                mma16(acc3[mi][ni], af[mi], &b3r[ni * 2]);
            }
        }
    }

    // epilogue: silu(s1) * s3 -> d_h (fp16)
    #pragma unroll
    for (int mi = 0; mi < 2; mi++)
    #pragma unroll
    for (int ni = 0; ni < 2; ni++)
    #pragma unroll
    for (int h = 0; h < 2; h++) {
        int lr = wm * 32 + mi * 16 + g + h * 8;
        if (m0 + lr < cnt) {
            int col = n0 + wn * 16 + ni * 8 + tg * 2;
            float v1a = acc1[mi][ni][h * 2], v1b = acc1[mi][ni][h * 2 + 1];
            float v3a = acc3[mi][ni][h * 2], v3b = acc3[mi][ni][h * 2 + 1];
            float h0 = v1a * v3a / (1.f + __expf(-v1a));
            float h1 = v1b * v3b / (1.f + __expf(-v1b));
            unsigned u = pk2(h0, h1);
            *(unsigned*)&d_h[((size_t)(e * SLOT + m0 + lr)) * FDIM + col] = u;
        }
    }
}

// ---------------- GEMM2: 128x64 tile, split-K x2, fp16 mma ------------------
__global__ __launch_bounds__(256, 4) void gemm2_kernel(const float* __restrict__ w2) {
    extern __shared__ __half smh[];
    __half* Ab = smh;                       // 4 * ROWH128
    __half* Bb = smh + 4 * ROWH128;         // 2 * ROWH64

    int e = blockIdx.y >> 2, mtile = blockIdx.y & 3;
    int cnt = d_count[e];
    int m0 = mtile * 128;
    if (m0 >= cnt) return;
    int n0 = blockIdx.x * 64;
    int kz = blockIdx.z;
    int kbase = kz * (FDIM / 2);

    int tid = threadIdx.x;
    // A cp.async: 2 chunks/thread (128 rows x 4 chunks)
    const __half* aptr[2]; unsigned aoffs[2];
    #pragma unroll
    for (int j = 0; j < 2; j++) {
        int gidx = tid + 256 * j;
        int row = gidx >> 2, c = gidx & 3;
        int rr = m0 + row; if (rr >= cnt) rr = cnt - 1;
        aptr[j]  = d_h + ((size_t)(e * SLOT) + rr) * FDIM + kbase + c * 8;
        aoffs[j] = (unsigned)(row * SSTH + c * 8) * 2;
    }
    // B LDG: row = tid>>2, 8 floats
    int brow = tid >> 2, bc = tid & 3;
    const float* bp = w2 + ((size_t)e * HDIM + n0 + brow) * FDIM + kbase + bc * 8;
    unsigned bsts = (unsigned)(brow * SSTH + bc * 8) * 2;

    unsigned uA = (unsigned)__cvta_generic_to_shared(Ab);

    const int NKT = (FDIM / 2) / 32;  // 64

    float4 pba = *(const float4*)bp, pbb = *(const float4*)(bp + 4);
    #pragma unroll
    for (int s = 0; s < 3; s++) {
        #pragma unroll
        for (int j = 0; j < 2; j++)
            cpa(uA + (unsigned)s * (ROWH128 * 2) + aoffs[j], aptr[j] + s * 32);
        CP_COMMIT;
    }

    int warp = tid >> 5, lane = tid & 31;
    int wm = warp >> 1, wn = warp & 1;     // 4 x 2 warps, warp tile 32x32
    int g = lane >> 2, tg = lane & 3;

    unsigned aoffm[2], boffp[2];
    #pragma unroll
    for (int mi = 0; mi < 2; mi++)
        aoffm[mi] = (unsigned)((wm * 32 + mi * 16 + (lane & 7) + ((lane >> 3) & 1) * 8) * SSTH
                               + (lane >> 4) * 8) * 2;
    #pragma unroll
    for (int p = 0; p < 2; p++)
        boffp[p] = (unsigned)((wn * 32 + p * 16 + (lane & 7) + ((lane >> 4) & 1) * 8) * SSTH
                              + ((lane >> 3) & 1) * 8) * 2;

    float acc[2][4][4] = {};

    for (int kt = 0; kt < NKT; kt++) {
        { uint4 u; u.x = pk2(pba.x, pba.y); u.y = pk2(pba.z, pba.w);
          u.z = pk2(pbb.x, pbb.y); u.w = pk2(pbb.z, pbb.w);
          *(uint4*)((char*)Bb + ((kt & 1) * (ROWH64 * 2) + bsts)) = u; }
        CP_WAIT2;
        __syncthreads();

        if (kt + 1 < NKT) {
            const float* p = bp + (kt + 1) * 32;
            pba = *(const float4*)p; pbb = *(const float4*)(p + 4);
        }
        if (kt + 3 < NKT) {
            #pragma unroll
            for (int j = 0; j < 2; j++)
                cpa(uA + (unsigned)((kt + 3) & 3) * (ROWH128 * 2) + aoffs[j], aptr[j] + (kt + 3) * 32);
        }
        CP_COMMIT;

        unsigned sAc = uA + (unsigned)(kt & 3) * (ROWH128 * 2);
        unsigned sBc = (unsigned)__cvta_generic_to_shared(Bb) + (unsigned)(kt & 1) * (ROWH64 * 2);

        #pragma unroll
        for (int ks = 0; ks < 2; ks++) {
            unsigned kb = (unsigned)ks * 32;
            unsigned af[2][4], br[2][4];
            ldsm4(af[0], sAc + aoffm[0] + kb);
            ldsm4(af[1], sAc + aoffm[1] + kb);
            ldsm4(br[0], sBc + boffp[0] + kb);
            ldsm4(br[1], sBc + boffp[1] + kb);
            #pragma unroll
            for (int p = 0; p < 2; p++)
            #pragma unroll
            for (int hn = 0; hn < 2; hn++) {
                int ni = p * 2 + hn;
                #pragma unroll
                for (int mi = 0; mi < 2; mi++)
                    mma16(acc[mi][ni], af[mi], &br[p][hn * 2]);
            }
        }
    }

    float* po = d_po2 + (size_t)kz * (NEXP * SLOT * HDIM);
    #pragma unroll
    for (int mi = 0; mi < 2; mi++)
    #pragma unroll
    for (int ni = 0; ni < 4; ni++)
    #pragma unroll
    for (int h = 0; h < 2; h++) {
        int lr = wm * 32 + mi * 16 + g + h * 8;
        if (m0 + lr < cnt) {
            float mult = d_mult[e * SLOT + m0 + lr];
            int col = n0 + wn * 32 + ni * 8 + tg * 2;
            float2 o;
            o.x = acc[mi][ni][h * 2]     * mult;
            o.y = acc[mi][ni][h * 2 + 1] * mult;
            *(float2*)&po[((size_t)(e * SLOT + m0 + lr)) * HDIM + col] = o;
        }
    }
}

// ---------------- finalize ---------------------------------------------------
__global__ void finalize_kernel(float* __restrict__ out) {
    int t = blockIdx.x;
    int i = threadIdx.x;
    int p0 = d_pidx[t * 2], p1 = d_pidx[t * 2 + 1];
    const float* po0 = d_po2;
    const float* po1 = d_po2 + (size_t)(NEXP * SLOT * HDIM);
    float4 a = ((const float4*)(po0 + (size_t)p0 * HDIM))[i];
    float4 b = ((const float4*)(po0 + (size_t)p1 * HDIM))[i];
    float4 c = ((const float4*)(po1 + (size_t)p0 * HDIM))[i];
    float4 d = ((const float4*)(po1 + (size_t)p1 * HDIM))[i];
    float4 o;
    o.x = (a.x + c.x) + (b.x + d.x);
    o.y = (a.y + c.y) + (b.y + d.y);
    o.z = (a.z + c.z) + (b.z + d.z);
    o.w = (a.w + c.w) + (b.w + d.w);
    ((float4*)(out + (size_t)t * HDIM))[i] = o;
}

// ---------------- launch ----------------------------------------------------
extern "C" void kernel_launch(void* const* d_in, const int* in_sizes, int n_in,
                              void* d_out, int out_size) {
    const float* x  = (const float*)d_in[0];
    const float* gw = (const float*)d_in[1];
    const float* w1 = (const float*)d_in[2];
    const float* w2 = (const float*)d_in[3];
    const float* w3 = (const float*)d_in[4];
    float* out = (float*)d_out;

    const int smem1 = 8 * ROWH64 * 2;                    // 40960 B
    const int smem2 = (4 * ROWH128 + 2 * ROWH64) * 2;    // 51200 B
    cudaFuncSetAttribute(gemm1_kernel, cudaFuncAttributeMaxDynamicSharedMemorySize, smem1);
    cudaFuncSetAttribute(gemm2_kernel, cudaFuncAttributeMaxDynamicSharedMemorySize, smem2);

    init_kernel<<<1, 32>>>();
    convx_kernel<<<TOKS * HDIM / 1024, 256>>>(x);
    routing_kernel<<<TOKS, 256>>>(x, gw);
    gemm1_kernel<<<dim3(FDIM / 64, NEXP * 8), 256, smem1>>>(w1, w3);
    gemm2_kernel<<<dim3(HDIM / 64, NEXP * 4, 2), 256, smem2>>>(w2);
    finalize_kernel<<<TOKS, 256>>>(out);
}

// round 14
// speedup vs baseline: 1.6117x; 1.1560x over previous
#include <cuda_runtime.h>
#include <cuda_fp16.h>
#include <cstdint>
#include <math.h>

#define TOKS 512
#define HDIM 1024
#define FDIM 4096
#define NEXP 8
#define SLOT 512
#define SSTH 40                    // halves per smem row (80 B, ldsm conflict-free)
#define ROWH64  (64 * SSTH)        // 2560 halves per 64-row stage
#define ROWH128 (128 * SSTH)       // 5120 halves per 128-row stage

// ---------------- scratch (static device globals) ---------------------------
__device__ __half d_xh[TOKS * HDIM];               // fp16 x (1 MB)
__device__ __half d_h[NEXP * SLOT * FDIM];         // fp16 intermediate h (32 MB)
__device__ __half d_po2[2 * NEXP * SLOT * HDIM];   // split-K partials (fp16, 16 MB)
__device__ int    d_count[NEXP];
__device__ int    d_tok[NEXP * SLOT];
__device__ float  d_mult[NEXP * SLOT];
__device__ int    d_pidx[TOKS * 2];

// ---------------- helpers ----------------------------------------------------
__device__ __forceinline__ unsigned pk2(float a, float b) {
    __half2 h = __floats2half2_rn(a, b);
    return *(unsigned*)&h;
}
__device__ __forceinline__ void mma16(float* c, const unsigned* a, const unsigned* b) {
    asm volatile(
        "mma.sync.aligned.m16n8k16.row.col.f32.f16.f16.f32 "
        "{%0,%1,%2,%3}, {%4,%5,%6,%7}, {%8,%9}, {%0,%1,%2,%3};"
        : "+f"(c[0]), "+f"(c[1]), "+f"(c[2]), "+f"(c[3])
        : "r"(a[0]), "r"(a[1]), "r"(a[2]), "r"(a[3]), "r"(b[0]), "r"(b[1]));
}
__device__ __forceinline__ void ldsm4(unsigned* r, unsigned addr) {
    asm volatile("ldmatrix.sync.aligned.m8n8.x4.shared.b16 {%0,%1,%2,%3}, [%4];"
        : "=r"(r[0]), "=r"(r[1]), "=r"(r[2]), "=r"(r[3]) : "r"(addr));
}
__device__ __forceinline__ void cpa(unsigned dst, const void* src) {
    asm volatile("cp.async.cg.shared.global [%0], [%1], 16;" :: "r"(dst), "l"(src));
}
#define CP_COMMIT asm volatile("cp.async.commit_group;")
#define CP_WAIT2  asm volatile("cp.async.wait_group 2;")

// ---------------- init / convx ----------------------------------------------
__global__ void init_kernel() {
    if (threadIdx.x < NEXP) d_count[threadIdx.x] = 0;
}
__global__ void convx_kernel(const float* __restrict__ x) {
    int i = (blockIdx.x * 256 + threadIdx.x) * 4;
    float4 v = *(const float4*)(x + i);
    uint2 o; o.x = pk2(v.x, v.y); o.y = pk2(v.z, v.w);
    *(uint2*)&d_xh[i] = o;
}

// ---------------- routing ---------------------------------------------------
__global__ void routing_kernel(const float* __restrict__ x,
                               const float* __restrict__ gw) {
    int t = blockIdx.x;
    int tid = threadIdx.x;
    int w = tid >> 5, lane = tid & 31;
    __shared__ float lg[NEXP];

    const float* xr = x + (size_t)t * HDIM;
    const float* gr = gw + (size_t)w * HDIM;
    float s = 0.f;
    for (int i = lane * 4; i < HDIM; i += 128) {
        float4 a = *(const float4*)(xr + i);
        float4 b = *(const float4*)(gr + i);
        s += a.x * b.x + a.y * b.y + a.z * b.z + a.w * b.w;
    }
    #pragma unroll
    for (int o = 16; o; o >>= 1) s += __shfl_xor_sync(0xFFFFFFFFu, s, o);
    if (lane == 0) lg[w] = s;
    __syncthreads();

    if (tid == 0) {
        float l[NEXP];
        #pragma unroll
        for (int e = 0; e < NEXP; e++) l[e] = lg[e];

        int s1 = 0;
        for (int e = 1; e < NEXP; e++) if (l[e] > l[s1]) s1 = e;
        float m1 = l[s1];
        int s2 = (s1 == 0) ? 1 : 0;
        for (int e = 0; e < NEXP; e++) { if (e == s1) continue; if (l[e] > l[s2]) s2 = e; }
        float m2 = l[s2];

        float mult1, mult2;
        {
            float keep[NEXP]; float mx = -1e30f;
            for (int e = 0; e < NEXP; e++) {
                float f = fmaxf(fabsf(l[e]), m1);
                keep[e] = ((m1 - l[e]) / f > 0.02f) ? -1e30f : l[e];
                mx = fmaxf(mx, keep[e]);
            }
            float sum = 0.f, num = 0.f;
            for (int e = 0; e < NEXP; e++) {
                float p = (keep[e] <= -1e30f) ? 0.f : expf(keep[e] - mx);
                sum += p; if (e == s1) num = p;
            }
            mult1 = num / sum;
        }
        {
            float keep[NEXP]; float mx = -1e30f;
            for (int e = 0; e < NEXP; e++) {
                float f = fmaxf(fabsf(l[e]), m2);
                bool msk = ((m2 - l[e]) / f > 0.02f) || (e == s1);
                keep[e] = msk ? -1e30f : l[e];
                mx = fmaxf(mx, keep[e]);
            }
            float sum = 0.f, num = 0.f;
            for (int e = 0; e < NEXP; e++) {
                float p = (keep[e] <= -1e30f) ? 0.f : expf(keep[e] - mx);
                sum += p; if (e == s2) num = p;
            }
            mult2 = num / sum;
        }

        int p = atomicAdd(&d_count[s1], 1);
        d_tok[s1 * SLOT + p] = t; d_mult[s1 * SLOT + p] = mult1;
        d_pidx[t * 2 + 0] = s1 * SLOT + p;
        p = atomicAdd(&d_count[s2], 1);
        d_tok[s2 * SLOT + p] = t; d_mult[s2 * SLOT + p] = mult2;
        d_pidx[t * 2 + 1] = s2 * SLOT + p;
    }
}

// ---------------- GEMM1: 64x64 tile, fused w1/w3, fp16 mma ------------------
// smem: A ring-4 (fp16, cp.async from d_xh) + B1/B3 double buf (LDG fp32 -> cvt)
// B prefetch reordered: LDG(kt+1) issues right after the store of kt's regs,
// BEFORE the wait/sync -> LDG->use distance ~= one full iteration.
__global__ __launch_bounds__(256, 3) void gemm1_kernel(const float* __restrict__ w1,
                                                       const float* __restrict__ w3) {
    extern __shared__ __half smh[];
    __half* Ab  = smh;                       // 4 * ROWH64
    __half* B1b = smh + 4 * ROWH64;          // 2 * ROWH64
    __half* B3b = smh + 6 * ROWH64;          // 2 * ROWH64

    int e = blockIdx.y >> 3, mtile = blockIdx.y & 7;
    int cnt = d_count[e];
    int m0 = mtile * 64;
    if (m0 >= cnt) return;
    int n0 = blockIdx.x * 64;

    int tid = threadIdx.x;
    int arow = tid >> 2, ac = tid & 3;
    int rr = m0 + arow; if (rr >= cnt) rr = cnt - 1;
    const __half* aptr = d_xh + (size_t)d_tok[e * SLOT + rr] * HDIM + ac * 8;
    unsigned aoffs = (unsigned)(arow * SSTH + ac * 8) * 2;

    const float* b1p = w1 + ((size_t)e * FDIM + n0 + arow) * HDIM + ac * 8;
    const float* b3p = w3 + ((size_t)e * FDIM + n0 + arow) * HDIM + ac * 8;
    unsigned bsts = (unsigned)(arow * SSTH + ac * 8) * 2;

    unsigned uA  = (unsigned)__cvta_generic_to_shared(Ab);
    unsigned uB1 = (unsigned)__cvta_generic_to_shared(B1b);
    unsigned uB3 = (unsigned)__cvta_generic_to_shared(B3b);

    const int NKT = HDIM / 32;  // 32

    float4 pb1a = *(const float4*)b1p, pb1b = *(const float4*)(b1p + 4);
    float4 pb3a = *(const float4*)b3p, pb3b = *(const float4*)(b3p + 4);
    #pragma unroll
    for (int s = 0; s < 3; s++) {
        cpa(uA + (unsigned)s * (ROWH64 * 2) + aoffs, aptr + s * 32);
        CP_COMMIT;
    }

    int warp = tid >> 5, lane = tid & 31;
    int wm = warp >> 2, wn = warp & 3;     // 2 x 4 warps, warp tile 32x16
    int g = lane >> 2, tg = lane & 3;

    unsigned aoffm[2], boff;
    #pragma unroll
    for (int mi = 0; mi < 2; mi++)
        aoffm[mi] = (unsigned)((wm * 32 + mi * 16 + (lane & 7) + ((lane >> 3) & 1) * 8) * SSTH
                               + (lane >> 4) * 8) * 2;
    boff = (unsigned)((wn * 16 + (lane & 7) + ((lane >> 4) & 1) * 8) * SSTH
                      + ((lane >> 3) & 1) * 8) * 2;

    float acc1[2][2][4] = {}, acc3[2][2][4] = {};

    for (int kt = 0; kt < NKT; kt++) {
        // store this k-tile's weights (regs loaded one iteration ago)
        { uint4 u; u.x = pk2(pb1a.x, pb1a.y); u.y = pk2(pb1a.z, pb1a.w);
          u.z = pk2(pb1b.x, pb1b.y); u.w = pk2(pb1b.z, pb1b.w);
          *(uint4*)((char*)B1b + ((kt & 1) * (ROWH64 * 2) + bsts)) = u; }
        { uint4 u; u.x = pk2(pb3a.x, pb3a.y); u.y = pk2(pb3a.z, pb3a.w);
          u.z = pk2(pb3b.x, pb3b.y); u.w = pk2(pb3b.z, pb3b.w);
          *(uint4*)((char*)B3b + ((kt & 1) * (ROWH64 * 2) + bsts)) = u; }

        // REORDERED: issue next B LDGs immediately (regs free, max latency cover)
        if (kt + 1 < NKT) {
            const float* p1 = b1p + (kt + 1) * 32;
            const float* p3 = b3p + (kt + 1) * 32;
            pb1a = *(const float4*)p1; pb1b = *(const float4*)(p1 + 4);
            pb3a = *(const float4*)p3; pb3b = *(const float4*)(p3 + 4);
        }

        CP_WAIT2;
        __syncthreads();

        if (kt + 3 < NKT)
            cpa(uA + (unsigned)((kt + 3) & 3) * (ROWH64 * 2) + aoffs, aptr + (kt + 3) * 32);
        CP_COMMIT;

        unsigned sAc  = uA  + (unsigned)(kt & 3) * (ROWH64 * 2);
        unsigned sB1c = uB1 + (unsigned)(kt & 1) * (ROWH64 * 2);
        unsigned sB3c = uB3 + (unsigned)(kt & 1) * (ROWH64 * 2);

        #pragma unroll
        for (int ks = 0; ks < 2; ks++) {
            unsigned kb = (unsigned)ks * 32;   // 16 halves
            unsigned af[2][4], b1r[4], b3r[4];
            ldsm4(af[0], sAc + aoffm[0] + kb);
            ldsm4(af[1], sAc + aoffm[1] + kb);
            ldsm4(b1r, sB1c + boff + kb);
            ldsm4(b3r, sB3c + boff + kb);
            #pragma unroll
            for (int ni = 0; ni < 2; ni++)
            #pragma unroll
            for (int mi = 0; mi < 2; mi++) {
                mma16(acc1[mi][ni], af[mi], &b1r[ni * 2]);
                mma16(acc3[mi][ni], af[mi], &b3r[ni * 2]);
            }
        }
    }

    // epilogue: silu(s1) * s3 -> d_h (fp16)
    #pragma unroll
    for (int mi = 0; mi < 2; mi++)
    #pragma unroll
    for (int ni = 0; ni < 2; ni++)
    #pragma unroll
    for (int h = 0; h < 2; h++) {
        int lr = wm * 32 + mi * 16 + g + h * 8;
        if (m0 + lr < cnt) {
            int col = n0 + wn * 16 + ni * 8 + tg * 2;
            float v1a = acc1[mi][ni][h * 2], v1b = acc1[mi][ni][h * 2 + 1];
            float v3a = acc3[mi][ni][h * 2], v3b = acc3[mi][ni][h * 2 + 1];
            float h0 = v1a * v3a / (1.f + __expf(-v1a));
            float h1 = v1b * v3b / (1.f + __expf(-v1b));
            unsigned u = pk2(h0, h1);
            *(unsigned*)&d_h[((size_t)(e * SLOT + m0 + lr)) * FDIM + col] = u;
        }
    }
}

// ---------------- GEMM2: 128x64 tile, split-K x2, fp16 mma ------------------
__global__ __launch_bounds__(256, 3) void gemm2_kernel(const float* __restrict__ w2) {
    extern __shared__ __half smh[];
    __half* Ab = smh;                       // 4 * ROWH128
    __half* Bb = smh + 4 * ROWH128;         // 2 * ROWH64

    int e = blockIdx.y >> 2, mtile = blockIdx.y & 3;
    int cnt = d_count[e];
    int m0 = mtile * 128;
    if (m0 >= cnt) return;
    int n0 = blockIdx.x * 64;
    int kz = blockIdx.z;
    int kbase = kz * (FDIM / 2);

    int tid = threadIdx.x;
    const __half* aptr[2]; unsigned aoffs[2];
    #pragma unroll
    for (int j = 0; j < 2; j++) {
        int gidx = tid + 256 * j;
        int row = gidx >> 2, c = gidx & 3;
        int rr = m0 + row; if (rr >= cnt) rr = cnt - 1;
        aptr[j]  = d_h + ((size_t)(e * SLOT) + rr) * FDIM + kbase + c * 8;
        aoffs[j] = (unsigned)(row * SSTH + c * 8) * 2;
    }
    int brow = tid >> 2, bc = tid & 3;
    const float* bp = w2 + ((size_t)e * HDIM + n0 + brow) * FDIM + kbase + bc * 8;
    unsigned bsts = (unsigned)(brow * SSTH + bc * 8) * 2;

    unsigned uA = (unsigned)__cvta_generic_to_shared(Ab);

    const int NKT = (FDIM / 2) / 32;  // 64

    float4 pba = *(const float4*)bp, pbb = *(const float4*)(bp + 4);
    #pragma unroll
    for (int s = 0; s < 3; s++) {
        #pragma unroll
        for (int j = 0; j < 2; j++)
            cpa(uA + (unsigned)s * (ROWH128 * 2) + aoffs[j], aptr[j] + s * 32);
        CP_COMMIT;
    }

    int warp = tid >> 5, lane = tid & 31;
    int wm = warp >> 1, wn = warp & 1;     // 4 x 2 warps, warp tile 32x32
    int g = lane >> 2, tg = lane & 3;

    unsigned aoffm[2], boffp[2];
    #pragma unroll
    for (int mi = 0; mi < 2; mi++)
        aoffm[mi] = (unsigned)((wm * 32 + mi * 16 + (lane & 7) + ((lane >> 3) & 1) * 8) * SSTH
                               + (lane >> 4) * 8) * 2;
    #pragma unroll
    for (int p = 0; p < 2; p++)
        boffp[p] = (unsigned)((wn * 32 + p * 16 + (lane & 7) + ((lane >> 4) & 1) * 8) * SSTH
                              + ((lane >> 3) & 1) * 8) * 2;

    float acc[2][4][4] = {};

    for (int kt = 0; kt < NKT; kt++) {
        { uint4 u; u.x = pk2(pba.x, pba.y); u.y = pk2(pba.z, pba.w);
          u.z = pk2(pbb.x, pbb.y); u.w = pk2(pbb.z, pbb.w);
          *(uint4*)((char*)Bb + ((kt & 1) * (ROWH64 * 2) + bsts)) = u; }

        // REORDERED: next B LDG before wait/sync
        if (kt + 1 < NKT) {
            const float* p = bp + (kt + 1) * 32;
            pba = *(const float4*)p; pbb = *(const float4*)(p + 4);
        }

        CP_WAIT2;
        __syncthreads();

        if (kt + 3 < NKT) {
            #pragma unroll
            for (int j = 0; j < 2; j++)
                cpa(uA + (unsigned)((kt + 3) & 3) * (ROWH128 * 2) + aoffs[j], aptr[j] + (kt + 3) * 32);
        }
        CP_COMMIT;

        unsigned sAc = uA + (unsigned)(kt & 3) * (ROWH128 * 2);
        unsigned sBc = (unsigned)__cvta_generic_to_shared(Bb) + (unsigned)(kt & 1) * (ROWH64 * 2);

        #pragma unroll
        for (int ks = 0; ks < 2; ks++) {
            unsigned kb = (unsigned)ks * 32;
            unsigned af[2][4], br[2][4];
            ldsm4(af[0], sAc + aoffm[0] + kb);
            ldsm4(af[1], sAc + aoffm[1] + kb);
            ldsm4(br[0], sBc + boffp[0] + kb);
            ldsm4(br[1], sBc + boffp[1] + kb);
            #pragma unroll
            for (int p = 0; p < 2; p++)
            #pragma unroll
            for (int hn = 0; hn < 2; hn++) {
                int ni = p * 2 + hn;
                #pragma unroll
                for (int mi = 0; mi < 2; mi++)
                    mma16(acc[mi][ni], af[mi], &br[p][hn * 2]);
            }
        }
    }

    // epilogue: fp16 partials (halves po traffic)
    __half* po = d_po2 + (size_t)kz * (NEXP * SLOT * HDIM);
    #pragma unroll
    for (int mi = 0; mi < 2; mi++)
    #pragma unroll
    for (int ni = 0; ni < 4; ni++)
    #pragma unroll
    for (int h = 0; h < 2; h++) {
        int lr = wm * 32 + mi * 16 + g + h * 8;
        if (m0 + lr < cnt) {
            float mult = d_mult[e * SLOT + m0 + lr];
            int col = n0 + wn * 32 + ni * 8 + tg * 2;
            unsigned u = pk2(acc[mi][ni][h * 2] * mult, acc[mi][ni][h * 2 + 1] * mult);
            *(unsigned*)&po[((size_t)(e * SLOT + m0 + lr)) * HDIM + col] = u;
        }
    }
}

// ---------------- finalize: out[t] = sum of 4 fp16 partials ------------------
__global__ void finalize_kernel(float* __restrict__ out) {
    int t = blockIdx.x;
    int i = threadIdx.x;                 // 256 threads x 4 floats = 1024
    int p0 = d_pidx[t * 2], p1 = d_pidx[t * 2 + 1];
    const __half* po0 = d_po2;
    const __half* po1 = d_po2 + (size_t)(NEXP * SLOT * HDIM);

    uint2 a = ((const uint2*)(po0 + (size_t)p0 * HDIM))[i];
    uint2 b = ((const uint2*)(po0 + (size_t)p1 * HDIM))[i];
    uint2 c = ((const uint2*)(po1 + (size_t)p0 * HDIM))[i];
    uint2 d = ((const uint2*)(po1 + (size_t)p1 * HDIM))[i];

    float2 a0 = __half22float2(*(__half2*)&a.x), a1 = __half22float2(*(__half2*)&a.y);
    float2 b0 = __half22float2(*(__half2*)&b.x), b1 = __half22float2(*(__half2*)&b.y);
    float2 c0 = __half22float2(*(__half2*)&c.x), c1 = __half22float2(*(__half2*)&c.y);
    float2 d0 = __half22float2(*(__half2*)&d.x), d1 = __half22float2(*(__half2*)&d.y);

    float4 o;
    o.x = (a0.x + c0.x) + (b0.x + d0.x);
    o.y = (a0.y + c0.y) + (b0.y + d0.y);
    o.z = (a1.x + c1.x) + (b1.x + d1.x);
    o.w = (a1.y + c1.y) + (b1.y + d1.y);
    ((float4*)(out + (size_t)t * HDIM))[i] = o;
}

// ---------------- launch ----------------------------------------------------
extern "C" void kernel_launch(void* const* d_in, const int* in_sizes, int n_in,
                              void* d_out, int out_size) {
    const float* x  = (const float*)d_in[0];
    const float* gw = (const float*)d_in[1];
    const float* w1 = (const float*)d_in[2];
    const float* w2 = (const float*)d_in[3];
    const float* w3 = (const float*)d_in[4];
    float* out = (float*)d_out;

    const int smem1 = 8 * ROWH64 * 2;                    // 40960 B
    const int smem2 = (4 * ROWH128 + 2 * ROWH64) * 2;    // 51200 B
    cudaFuncSetAttribute(gemm1_kernel, cudaFuncAttributeMaxDynamicSharedMemorySize, smem1);
    cudaFuncSetAttribute(gemm2_kernel, cudaFuncAttributeMaxDynamicSharedMemorySize, smem2);

    init_kernel<<<1, 32>>>();
    convx_kernel<<<TOKS * HDIM / 1024, 256>>>(x);
    routing_kernel<<<TOKS, 256>>>(x, gw);
    gemm1_kernel<<<dim3(FDIM / 64, NEXP * 8), 256, smem1>>>(w1, w3);
    gemm2_kernel<<<dim3(HDIM / 64, NEXP * 4, 2), 256, smem2>>>(w2);
    finalize_kernel<<<TOKS, 256>>>(out);
}

// round 15
// speedup vs baseline: 1.6296x; 1.0111x over previous
#include <cuda_runtime.h>
#include <cuda_fp16.h>
#include <cstdint>
#include <math.h>

#define TOKS 512
#define HDIM 1024
#define FDIM 4096
#define NEXP 8
#define SLOT 512
#define SSTH 40                       // halves per A smem row (80 B)
#define SSTF 36                       // floats per B smem row (144 B)
#define A64H  (64 * SSTH)             // 2560 halves / stage (gemm1 A)
#define ROWH64  (64 * SSTH)
#define ROWH128 (128 * SSTH)          // gemm2 A stage halves
#define BSTF  (64 * SSTF)             // 2304 floats / stage (gemm1 B)

// ---------------- scratch (static device globals) ---------------------------
__device__ __half d_xh[TOKS * HDIM];               // fp16 x
__device__ __half d_h[NEXP * SLOT * FDIM];         // fp16 intermediate h
__device__ __half d_po2[2 * NEXP * SLOT * HDIM];   // split-K partials (fp16)
__device__ int    d_count[NEXP];
__device__ int    d_tok[NEXP * SLOT];
__device__ float  d_mult[NEXP * SLOT];
__device__ int    d_pidx[TOKS * 2];

// ---------------- helpers ----------------------------------------------------
__device__ __forceinline__ unsigned pk2(float a, float b) {
    __half2 h = __floats2half2_rn(a, b);
    return *(unsigned*)&h;
}
__device__ __forceinline__ void mma16(float* c, const unsigned* a, const unsigned* b) {
    asm volatile(
        "mma.sync.aligned.m16n8k16.row.col.f32.f16.f16.f32 "
        "{%0,%1,%2,%3}, {%4,%5,%6,%7}, {%8,%9}, {%0,%1,%2,%3};"
        : "+f"(c[0]), "+f"(c[1]), "+f"(c[2]), "+f"(c[3])
        : "r"(a[0]), "r"(a[1]), "r"(a[2]), "r"(a[3]), "r"(b[0]), "r"(b[1]));
}
__device__ __forceinline__ void ldsm4(unsigned* r, unsigned addr) {
    asm volatile("ldmatrix.sync.aligned.m8n8.x4.shared.b16 {%0,%1,%2,%3}, [%4];"
        : "=r"(r[0]), "=r"(r[1]), "=r"(r[2]), "=r"(r[3]) : "r"(addr));
}
__device__ __forceinline__ void cpa(unsigned dst, const void* src) {
    asm volatile("cp.async.cg.shared.global [%0], [%1], 16;" :: "r"(dst), "l"(src));
}
#define CP_COMMIT asm volatile("cp.async.commit_group;")
#define CP_WAIT1  asm volatile("cp.async.wait_group 1;")
#define CP_WAIT2  asm volatile("cp.async.wait_group 2;")

// build B fragment pair from fp32 smem row (n-major, SSTF floats/row)
__device__ __forceinline__ void bfrag(const float* rowp, unsigned* br) {
    float2 lo = *(const float2*)rowp;
    float2 hi = *(const float2*)(rowp + 8);
    br[0] = pk2(lo.x, lo.y);
    br[1] = pk2(hi.x, hi.y);
}

// ---------------- init -------------------------------------------------------
__global__ void init_kernel() {
    if (threadIdx.x < NEXP) d_count[threadIdx.x] = 0;
}

// ---------------- routing (fused with x -> fp16 conversion) ------------------
__global__ void routing_kernel(const float* __restrict__ x,
                               const float* __restrict__ gw) {
    int t = blockIdx.x;
    int tid = threadIdx.x;
    int w = tid >> 5, lane = tid & 31;
    __shared__ float lg[NEXP];

    const float* xr = x + (size_t)t * HDIM;

    // convert this token's row to fp16 (256 threads x 1 float4)
    {
        float4 v = ((const float4*)xr)[tid];
        uint2 o; o.x = pk2(v.x, v.y); o.y = pk2(v.z, v.w);
        ((uint2*)(d_xh + (size_t)t * HDIM))[tid] = o;
    }

    const float* gr = gw + (size_t)w * HDIM;
    float s = 0.f;
    for (int i = lane * 4; i < HDIM; i += 128) {
        float4 a = *(const float4*)(xr + i);
        float4 b = *(const float4*)(gr + i);
        s += a.x * b.x + a.y * b.y + a.z * b.z + a.w * b.w;
    }
    #pragma unroll
    for (int o = 16; o; o >>= 1) s += __shfl_xor_sync(0xFFFFFFFFu, s, o);
    if (lane == 0) lg[w] = s;
    __syncthreads();

    if (tid == 0) {
        float l[NEXP];
        #pragma unroll
        for (int e = 0; e < NEXP; e++) l[e] = lg[e];

        int s1 = 0;
        for (int e = 1; e < NEXP; e++) if (l[e] > l[s1]) s1 = e;
        float m1 = l[s1];
        int s2 = (s1 == 0) ? 1 : 0;
        for (int e = 0; e < NEXP; e++) { if (e == s1) continue; if (l[e] > l[s2]) s2 = e; }
        float m2 = l[s2];

        float mult1, mult2;
        {
            float keep[NEXP]; float mx = -1e30f;
            for (int e = 0; e < NEXP; e++) {
                float f = fmaxf(fabsf(l[e]), m1);
                keep[e] = ((m1 - l[e]) / f > 0.02f) ? -1e30f : l[e];
                mx = fmaxf(mx, keep[e]);
            }
            float sum = 0.f, num = 0.f;
            for (int e = 0; e < NEXP; e++) {
                float p = (keep[e] <= -1e30f) ? 0.f : expf(keep[e] - mx);
                sum += p; if (e == s1) num = p;
            }
            mult1 = num / sum;
        }
        {
            float keep[NEXP]; float mx = -1e30f;
            for (int e = 0; e < NEXP; e++) {
                float f = fmaxf(fabsf(l[e]), m2);
                bool msk = ((m2 - l[e]) / f > 0.02f) || (e == s1);
                keep[e] = msk ? -1e30f : l[e];
                mx = fmaxf(mx, keep[e]);
            }
            float sum = 0.f, num = 0.f;
            for (int e = 0; e < NEXP; e++) {
                float p = (keep[e] <= -1e30f) ? 0.f : expf(keep[e] - mx);
                sum += p; if (e == s2) num = p;
            }
            mult2 = num / sum;
        }

        int p = atomicAdd(&d_count[s1], 1);
        d_tok[s1 * SLOT + p] = t; d_mult[s1 * SLOT + p] = mult1;
        d_pidx[t * 2 + 0] = s1 * SLOT + p;
        p = atomicAdd(&d_count[s2], 1);
        d_tok[s2 * SLOT + p] = t; d_mult[s2 * SLOT + p] = mult2;
        d_pidx[t * 2 + 1] = s2 * SLOT + p;
    }
}

// ---------------- GEMM1: 64x64, fused w1/w3, all-cp.async (R6, 156us) --------
__global__ __launch_bounds__(256, 3) void gemm1_kernel(const float* __restrict__ w1,
                                                       const float* __restrict__ w3) {
    extern __shared__ char smraw[];
    __half* Ab  = (__half*)smraw;                         // 3 * A64H halves
    float*  B1b = (float*)(smraw + 3 * A64H * 2);         // 3 * BSTF floats
    float*  B3b = (float*)(smraw + 3 * A64H * 2 + 3 * BSTF * 4);

    int e = blockIdx.y >> 3, mtile = blockIdx.y & 7;
    int cnt = d_count[e];
    int m0 = mtile * 64;
    if (m0 >= cnt) return;
    int n0 = blockIdx.x * 64;

    int tid = threadIdx.x;
    // A cp.async: 1 chunk/thread (64 rows x 4 chunks of 8 halves)
    int arow = tid >> 2, ac = tid & 3;
    int rr = m0 + arow; if (rr >= cnt) rr = cnt - 1;
    const __half* aptr = d_xh + (size_t)d_tok[e * SLOT + rr] * HDIM + ac * 8;
    unsigned aoffs = (unsigned)(arow * SSTH + ac * 8) * 2;

    // B cp.async: 2 chunks/thread each matrix (64 rows x 8 chunks of 4 floats)
    const float* b1p[2]; const float* b3p[2]; unsigned boffs[2];
    #pragma unroll
    for (int j = 0; j < 2; j++) {
        int gidx = tid + 256 * j;
        int row = gidx >> 3, c = gidx & 7;
        b1p[j] = w1 + ((size_t)e * FDIM + n0 + row) * HDIM + c * 4;
        b3p[j] = w3 + ((size_t)e * FDIM + n0 + row) * HDIM + c * 4;
        boffs[j] = (unsigned)(row * SSTF + c * 4) * 4;
    }

    unsigned uA  = (unsigned)__cvta_generic_to_shared(Ab);
    unsigned uB1 = (unsigned)__cvta_generic_to_shared(B1b);
    unsigned uB3 = (unsigned)__cvta_generic_to_shared(B3b);

    const int NKT = HDIM / 32;  // 32

    #pragma unroll
    for (int s = 0; s < 2; s++) {
        cpa(uA + (unsigned)s * (A64H * 2) + aoffs, aptr + s * 32);
        #pragma unroll
        for (int j = 0; j < 2; j++) {
            cpa(uB1 + (unsigned)s * (BSTF * 4) + boffs[j], b1p[j] + s * 32);
            cpa(uB3 + (unsigned)s * (BSTF * 4) + boffs[j], b3p[j] + s * 32);
        }
        CP_COMMIT;
    }

    int warp = tid >> 5, lane = tid & 31;
    int wm = warp >> 2, wn = warp & 3;     // 2 x 4 warps, warp tile 32x16
    int g = lane >> 2, tg = lane & 3;
    int bq = lane & 3, bn = lane >> 2;

    unsigned aoffm[2];
    #pragma unroll
    for (int mi = 0; mi < 2; mi++)
        aoffm[mi] = (unsigned)((wm * 32 + mi * 16 + (lane & 7) + ((lane >> 3) & 1) * 8) * SSTH
                               + (lane >> 4) * 8) * 2;

    float acc1[2][2][4] = {}, acc3[2][2][4] = {};

    for (int kt = 0; kt < NKT; kt++) {
        CP_WAIT1;
        __syncthreads();
        int kn = kt + 2;
        if (kn < NKT) {
            int st = kn % 3;
            cpa(uA + (unsigned)st * (A64H * 2) + aoffs, aptr + kn * 32);
            #pragma unroll
            for (int j = 0; j < 2; j++) {
                cpa(uB1 + (unsigned)st * (BSTF * 4) + boffs[j], b1p[j] + kn * 32);
                cpa(uB3 + (unsigned)st * (BSTF * 4) + boffs[j], b3p[j] + kn * 32);
            }
        }
        CP_COMMIT;

        unsigned sAc = uA + (unsigned)(kt % 3) * (A64H * 2);
        const float* B1c = B1b + (kt % 3) * BSTF;
        const float* B3c = B3b + (kt % 3) * BSTF;

        #pragma unroll
        for (int ks = 0; ks < 2; ks++) {
            unsigned af[2][4];
            ldsm4(af[0], sAc + aoffm[0] + ks * 32);
            ldsm4(af[1], sAc + aoffm[1] + ks * 32);
            int k0 = ks * 16 + 2 * bq;
            #pragma unroll
            for (int ni = 0; ni < 2; ni++) {
                int rowb = (wn * 16 + ni * 8 + bn) * SSTF + k0;
                unsigned br1[2], br3[2];
                bfrag(B1c + rowb, br1);
                bfrag(B3c + rowb, br3);
                #pragma unroll
                for (int mi = 0; mi < 2; mi++) {
                    mma16(acc1[mi][ni], af[mi], br1);
                    mma16(acc3[mi][ni], af[mi], br3);
                }
            }
        }
    }

    // epilogue: silu(s1) * s3 -> d_h (fp16)
    #pragma unroll
    for (int mi = 0; mi < 2; mi++)
    #pragma unroll
    for (int ni = 0; ni < 2; ni++)
    #pragma unroll
    for (int h = 0; h < 2; h++) {
        int lr = wm * 32 + mi * 16 + g + h * 8;
        if (m0 + lr < cnt) {
            int col = n0 + wn * 16 + ni * 8 + tg * 2;
            float v1a = acc1[mi][ni][h * 2], v1b = acc1[mi][ni][h * 2 + 1];
            float v3a = acc3[mi][ni][h * 2], v3b = acc3[mi][ni][h * 2 + 1];
            float h0 = v1a * v3a / (1.f + __expf(-v1a));
            float h1 = v1b * v3b / (1.f + __expf(-v1b));
            unsigned u = pk2(h0, h1);
            *(unsigned*)&d_h[((size_t)(e * SLOT + m0 + lr)) * FDIM + col] = u;
        }
    }
}

// ---------------- GEMM2: 128x64, split-K x2, fp16 mma (R5) -------------------
__global__ __launch_bounds__(256, 3) void gemm2_kernel(const float* __restrict__ w2) {
    extern __shared__ __half smh[];
    __half* Ab = smh;                       // 4 * ROWH128
    __half* Bb = smh + 4 * ROWH128;         // 2 * ROWH64

    int e = blockIdx.y >> 2, mtile = blockIdx.y & 3;
    int cnt = d_count[e];
    int m0 = mtile * 128;
    if (m0 >= cnt) return;
    int n0 = blockIdx.x * 64;
    int kz = blockIdx.z;
    int kbase = kz * (FDIM / 2);

    int tid = threadIdx.x;
    const __half* aptr[2]; unsigned aoffs[2];
    #pragma unroll
    for (int j = 0; j < 2; j++) {
        int gidx = tid + 256 * j;
        int row = gidx >> 2, c = gidx & 3;
        int rr = m0 + row; if (rr >= cnt) rr = cnt - 1;
        aptr[j]  = d_h + ((size_t)(e * SLOT) + rr) * FDIM + kbase + c * 8;
        aoffs[j] = (unsigned)(row * SSTH + c * 8) * 2;
    }
    int brow = tid >> 2, bc = tid & 3;
    const float* bp = w2 + ((size_t)e * HDIM + n0 + brow) * FDIM + kbase + bc * 8;
    unsigned bsts = (unsigned)(brow * SSTH + bc * 8) * 2;

    unsigned uA = (unsigned)__cvta_generic_to_shared(Ab);

    const int NKT = (FDIM / 2) / 32;  // 64

    float4 pba = *(const float4*)bp, pbb = *(const float4*)(bp + 4);
    #pragma unroll
    for (int s = 0; s < 3; s++) {
        #pragma unroll
        for (int j = 0; j < 2; j++)
            cpa(uA + (unsigned)s * (ROWH128 * 2) + aoffs[j], aptr[j] + s * 32);
        CP_COMMIT;
    }

    int warp = tid >> 5, lane = tid & 31;
    int wm = warp >> 1, wn = warp & 1;     // 4 x 2 warps, warp tile 32x32
    int g = lane >> 2, tg = lane & 3;

    unsigned aoffm[2], boffp[2];
    #pragma unroll
    for (int mi = 0; mi < 2; mi++)
        aoffm[mi] = (unsigned)((wm * 32 + mi * 16 + (lane & 7) + ((lane >> 3) & 1) * 8) * SSTH
                               + (lane >> 4) * 8) * 2;
    #pragma unroll
    for (int p = 0; p < 2; p++)
        boffp[p] = (unsigned)((wn * 32 + p * 16 + (lane & 7) + ((lane >> 4) & 1) * 8) * SSTH
                              + ((lane >> 3) & 1) * 8) * 2;

    float acc[2][4][4] = {};

    for (int kt = 0; kt < NKT; kt++) {
        { uint4 u; u.x = pk2(pba.x, pba.y); u.y = pk2(pba.z, pba.w);
          u.z = pk2(pbb.x, pbb.y); u.w = pk2(pbb.z, pbb.w);
          *(uint4*)((char*)Bb + ((kt & 1) * (ROWH64 * 2) + bsts)) = u; }
        CP_WAIT2;
        __syncthreads();

        if (kt + 1 < NKT) {
            const float* p = bp + (kt + 1) * 32;
            pba = *(const float4*)p; pbb = *(const float4*)(p + 4);
        }
        if (kt + 3 < NKT) {
            #pragma unroll
            for (int j = 0; j < 2; j++)
                cpa(uA + (unsigned)((kt + 3) & 3) * (ROWH128 * 2) + aoffs[j], aptr[j] + (kt + 3) * 32);
        }
        CP_COMMIT;

        unsigned sAc = uA + (unsigned)(kt & 3) * (ROWH128 * 2);
        unsigned sBc = (unsigned)__cvta_generic_to_shared(Bb) + (unsigned)(kt & 1) * (ROWH64 * 2);

        #pragma unroll
        for (int ks = 0; ks < 2; ks++) {
            unsigned kb = (unsigned)ks * 32;
            unsigned af[2][4], br[2][4];
            ldsm4(af[0], sAc + aoffm[0] + kb);
            ldsm4(af[1], sAc + aoffm[1] + kb);
            ldsm4(br[0], sBc + boffp[0] + kb);
            ldsm4(br[1], sBc + boffp[1] + kb);
            #pragma unroll
            for (int p = 0; p < 2; p++)
            #pragma unroll
            for (int hn = 0; hn < 2; hn++) {
                int ni = p * 2 + hn;
                #pragma unroll
                for (int mi = 0; mi < 2; mi++)
                    mma16(acc[mi][ni], af[mi], &br[p][hn * 2]);
            }
        }
    }

    // epilogue: fp16 partials (halves po traffic)
    __half* po = d_po2 + (size_t)kz * (NEXP * SLOT * HDIM);
    #pragma unroll
    for (int mi = 0; mi < 2; mi++)
    #pragma unroll
    for (int ni = 0; ni < 4; ni++)
    #pragma unroll
    for (int h = 0; h < 2; h++) {
        int lr = wm * 32 + mi * 16 + g + h * 8;
        if (m0 + lr < cnt) {
            float mult = d_mult[e * SLOT + m0 + lr];
            int col = n0 + wn * 32 + ni * 8 + tg * 2;
            unsigned u = pk2(acc[mi][ni][h * 2] * mult, acc[mi][ni][h * 2 + 1] * mult);
            *(unsigned*)&po[((size_t)(e * SLOT + m0 + lr)) * HDIM + col] = u;
        }
    }
}

// ---------------- finalize: out[t] = sum of fp16 partials --------------------
__global__ void finalize_kernel(float* __restrict__ out) {
    int t = blockIdx.x;
    int i = threadIdx.x;                 // 256 threads x 4 floats = 1024
    int p0 = d_pidx[t * 2], p1 = d_pidx[t * 2 + 1];
    const __half* po0 = d_po2;
    const __half* po1 = d_po2 + (size_t)(NEXP * SLOT * HDIM);

    uint2 a = ((const uint2*)(po0 + (size_t)p0 * HDIM))[i];
    uint2 b = ((const uint2*)(po0 + (size_t)p1 * HDIM))[i];
    uint2 c = ((const uint2*)(po1 + (size_t)p0 * HDIM))[i];
    uint2 d = ((const uint2*)(po1 + (size_t)p1 * HDIM))[i];

    float2 a0 = __half22float2(*(__half2*)&a.x), a1 = __half22float2(*(__half2*)&a.y);
    float2 b0 = __half22float2(*(__half2*)&b.x), b1 = __half22float2(*(__half2*)&b.y);
    float2 c0 = __half22float2(*(__half2*)&c.x), c1 = __half22float2(*(__half2*)&c.y);
    float2 d0 = __half22float2(*(__half2*)&d.x), d1 = __half22float2(*(__half2*)&d.y);

    float4 o;
    o.x = (a0.x + c0.x) + (b0.x + d0.x);
    o.y = (a0.y + c0.y) + (b0.y + d0.y);
    o.z = (a1.x + c1.x) + (b1.x + d1.x);
    o.w = (a1.y + c1.y) + (b1.y + d1.y);
    ((float4*)(out + (size_t)t * HDIM))[i] = o;
}

// ---------------- launch ----------------------------------------------------
extern "C" void kernel_launch(void* const* d_in, const int* in_sizes, int n_in,
                              void* d_out, int out_size) {
    const float* x  = (const float*)d_in[0];
    const float* gw = (const float*)d_in[1];
    const float* w1 = (const float*)d_in[2];
    const float* w2 = (const float*)d_in[3];
    const float* w3 = (const float*)d_in[4];
    float* out = (float*)d_out;

    const int smem1 = 3 * A64H * 2 + 6 * BSTF * 4;       // 70656 B
    const int smem2 = (4 * ROWH128 + 2 * ROWH64) * 2;    // 51200 B
    cudaFuncSetAttribute(gemm1_kernel, cudaFuncAttributeMaxDynamicSharedMemorySize, smem1);
    cudaFuncSetAttribute(gemm2_kernel, cudaFuncAttributeMaxDynamicSharedMemorySize, smem2);

    init_kernel<<<1, 32>>>();
    routing_kernel<<<TOKS, 256>>>(x, gw);
    gemm1_kernel<<<dim3(FDIM / 64, NEXP * 8), 256, smem1>>>(w1, w3);
    gemm2_kernel<<<dim3(HDIM / 64, NEXP * 4, 2), 256, smem2>>>(w2);
    finalize_kernel<<<TOKS, 256>>>(out);
}

// round 16
// speedup vs baseline: 1.6403x; 1.0066x over previous
#include <cuda_runtime.h>
#include <cuda_fp16.h>
#include <cstdint>
#include <math.h>

#define TOKS 512
#define HDIM 1024
#define FDIM 4096
#define NEXP 8
#define SLOT 512
#define SSTH 40                       // halves per fp16 smem row (80 B)
#define SSTF 36                       // floats per fp32 B smem row (144 B)
#define A64H  (64 * SSTH)             // 2560 halves / stage (gemm1 A)
#define ROWH64  (64 * SSTH)
#define ROWH128 (128 * SSTH)          // gemm2 A stage halves
#define BSTF  (64 * SSTF)             // 2304 floats / stage (gemm1 B)

// ---------------- scratch (static device globals) ---------------------------
__device__ __half d_xh[TOKS * HDIM];               // fp16 x (1 MB)
__device__ __half d_h[NEXP * SLOT * FDIM];         // fp16 intermediate h (32 MB)
__device__ float  d_po2[2 * NEXP * SLOT * HDIM];   // split-K partials (fp32)
__device__ int    d_count[NEXP];
__device__ int    d_tok[NEXP * SLOT];
__device__ float  d_mult[NEXP * SLOT];
__device__ int    d_pidx[TOKS * 2];

// ---------------- helpers ----------------------------------------------------
__device__ __forceinline__ unsigned pk2(float a, float b) {
    __half2 h = __floats2half2_rn(a, b);
    return *(unsigned*)&h;
}
__device__ __forceinline__ void mma16(float* c, const unsigned* a, const unsigned* b) {
    asm volatile(
        "mma.sync.aligned.m16n8k16.row.col.f32.f16.f16.f32 "
        "{%0,%1,%2,%3}, {%4,%5,%6,%7}, {%8,%9}, {%0,%1,%2,%3};"
        : "+f"(c[0]), "+f"(c[1]), "+f"(c[2]), "+f"(c[3])
        : "r"(a[0]), "r"(a[1]), "r"(a[2]), "r"(a[3]), "r"(b[0]), "r"(b[1]));
}
__device__ __forceinline__ void ldsm4(unsigned* r, unsigned addr) {
    asm volatile("ldmatrix.sync.aligned.m8n8.x4.shared.b16 {%0,%1,%2,%3}, [%4];"
        : "=r"(r[0]), "=r"(r[1]), "=r"(r[2]), "=r"(r[3]) : "r"(addr));
}
__device__ __forceinline__ void cpa(unsigned dst, const void* src) {
    asm volatile("cp.async.cg.shared.global [%0], [%1], 16;" :: "r"(dst), "l"(src));
}
#define CP_COMMIT asm volatile("cp.async.commit_group;")
#define CP_WAIT1  asm volatile("cp.async.wait_group 1;")
#define CP_WAIT2  asm volatile("cp.async.wait_group 2;")

// build B fragment pair from fp32 smem row (n-major, SSTF floats/row)
__device__ __forceinline__ void bfrag(const float* rowp, unsigned* br) {
    float2 lo = *(const float2*)rowp;
    float2 hi = *(const float2*)(rowp + 8);
    br[0] = pk2(lo.x, lo.y);
    br[1] = pk2(hi.x, hi.y);
}

// ---------------- init / convx ----------------------------------------------
__global__ void init_kernel() {
    if (threadIdx.x < NEXP) d_count[threadIdx.x] = 0;
}
__global__ void convx_kernel(const float* __restrict__ x) {
    int i = (blockIdx.x * 256 + threadIdx.x) * 4;
    float4 v = *(const float4*)(x + i);
    uint2 o; o.x = pk2(v.x, v.y); o.y = pk2(v.z, v.w);
    *(uint2*)&d_xh[i] = o;
}

// ---------------- routing ---------------------------------------------------
__global__ void routing_kernel(const float* __restrict__ x,
                               const float* __restrict__ gw) {
    int t = blockIdx.x;
    int tid = threadIdx.x;
    int w = tid >> 5, lane = tid & 31;
    __shared__ float lg[NEXP];

    const float* xr = x + (size_t)t * HDIM;
    const float* gr = gw + (size_t)w * HDIM;
    float s = 0.f;
    for (int i = lane * 4; i < HDIM; i += 128) {
        float4 a = *(const float4*)(xr + i);
        float4 b = *(const float4*)(gr + i);
        s += a.x * b.x + a.y * b.y + a.z * b.z + a.w * b.w;
    }
    #pragma unroll
    for (int o = 16; o; o >>= 1) s += __shfl_xor_sync(0xFFFFFFFFu, s, o);
    if (lane == 0) lg[w] = s;
    __syncthreads();

    if (tid == 0) {
        float l[NEXP];
        #pragma unroll
        for (int e = 0; e < NEXP; e++) l[e] = lg[e];

        int s1 = 0;
        for (int e = 1; e < NEXP; e++) if (l[e] > l[s1]) s1 = e;
        float m1 = l[s1];
        int s2 = (s1 == 0) ? 1 : 0;
        for (int e = 0; e < NEXP; e++) { if (e == s1) continue; if (l[e] > l[s2]) s2 = e; }
        float m2 = l[s2];

        float mult1, mult2;
        {
            float keep[NEXP]; float mx = -1e30f;
            for (int e = 0; e < NEXP; e++) {
                float f = fmaxf(fabsf(l[e]), m1);
                keep[e] = ((m1 - l[e]) / f > 0.02f) ? -1e30f : l[e];
                mx = fmaxf(mx, keep[e]);
            }
            float sum = 0.f, num = 0.f;
            for (int e = 0; e < NEXP; e++) {
                float p = (keep[e] <= -1e30f) ? 0.f : expf(keep[e] - mx);
                sum += p; if (e == s1) num = p;
            }
            mult1 = num / sum;
        }
        {
            float keep[NEXP]; float mx = -1e30f;
            for (int e = 0; e < NEXP; e++) {
                float f = fmaxf(fabsf(l[e]), m2);
                bool msk = ((m2 - l[e]) / f > 0.02f) || (e == s1);
                keep[e] = msk ? -1e30f : l[e];
                mx = fmaxf(mx, keep[e]);
            }
            float sum = 0.f, num = 0.f;
            for (int e = 0; e < NEXP; e++) {
                float p = (keep[e] <= -1e30f) ? 0.f : expf(keep[e] - mx);
                sum += p; if (e == s2) num = p;
            }
            mult2 = num / sum;
        }

        int p = atomicAdd(&d_count[s1], 1);
        d_tok[s1 * SLOT + p] = t; d_mult[s1 * SLOT + p] = mult1;
        d_pidx[t * 2 + 0] = s1 * SLOT + p;
        p = atomicAdd(&d_count[s2], 1);
        d_tok[s2 * SLOT + p] = t; d_mult[s2 * SLOT + p] = mult2;
        d_pidx[t * 2 + 1] = s2 * SLOT + p;
    }
}

// ---------------- GEMM1: 64x64, fused w1/w3, all-cp.async (R6, 156us) --------
__global__ __launch_bounds__(256, 3) void gemm1_kernel(const float* __restrict__ w1,
                                                       const float* __restrict__ w3) {
    extern __shared__ char smraw[];
    __half* Ab  = (__half*)smraw;                         // 3 * A64H halves
    float*  B1b = (float*)(smraw + 3 * A64H * 2);         // 3 * BSTF floats
    float*  B3b = (float*)(smraw + 3 * A64H * 2 + 3 * BSTF * 4);

    int e = blockIdx.y >> 3, mtile = blockIdx.y & 7;
    int cnt = d_count[e];
    int m0 = mtile * 64;
    if (m0 >= cnt) return;
    int n0 = blockIdx.x * 64;

    int tid = threadIdx.x;
    // A cp.async: 1 chunk/thread (64 rows x 4 chunks of 8 halves)
    int arow = tid >> 2, ac = tid & 3;
    int rr = m0 + arow; if (rr >= cnt) rr = cnt - 1;
    const __half* aptr = d_xh + (size_t)d_tok[e * SLOT + rr] * HDIM + ac * 8;
    unsigned aoffs = (unsigned)(arow * SSTH + ac * 8) * 2;

    // B cp.async: 2 chunks/thread each matrix (64 rows x 8 chunks of 4 floats)
    const float* b1p[2]; const float* b3p[2]; unsigned boffs[2];
    #pragma unroll
    for (int j = 0; j < 2; j++) {
        int gidx = tid + 256 * j;
        int row = gidx >> 3, c = gidx & 7;
        b1p[j] = w1 + ((size_t)e * FDIM + n0 + row) * HDIM + c * 4;
        b3p[j] = w3 + ((size_t)e * FDIM + n0 + row) * HDIM + c * 4;
        boffs[j] = (unsigned)(row * SSTF + c * 4) * 4;
    }

    unsigned uA  = (unsigned)__cvta_generic_to_shared(Ab);
    unsigned uB1 = (unsigned)__cvta_generic_to_shared(B1b);
    unsigned uB3 = (unsigned)__cvta_generic_to_shared(B3b);

    const int NKT = HDIM / 32;  // 32

    #pragma unroll
    for (int s = 0; s < 2; s++) {
        cpa(uA + (unsigned)s * (A64H * 2) + aoffs, aptr + s * 32);
        #pragma unroll
        for (int j = 0; j < 2; j++) {
            cpa(uB1 + (unsigned)s * (BSTF * 4) + boffs[j], b1p[j] + s * 32);
            cpa(uB3 + (unsigned)s * (BSTF * 4) + boffs[j], b3p[j] + s * 32);
        }
        CP_COMMIT;
    }

    int warp = tid >> 5, lane = tid & 31;
    int wm = warp >> 2, wn = warp & 3;     // 2 x 4 warps, warp tile 32x16
    int g = lane >> 2, tg = lane & 3;
    int bq = lane & 3, bn = lane >> 2;

    unsigned aoffm[2];
    #pragma unroll
    for (int mi = 0; mi < 2; mi++)
        aoffm[mi] = (unsigned)((wm * 32 + mi * 16 + (lane & 7) + ((lane >> 3) & 1) * 8) * SSTH
                               + (lane >> 4) * 8) * 2;

    float acc1[2][2][4] = {}, acc3[2][2][4] = {};

    for (int kt = 0; kt < NKT; kt++) {
        CP_WAIT1;
        __syncthreads();
        int kn = kt + 2;
        if (kn < NKT) {
            int st = kn % 3;
            cpa(uA + (unsigned)st * (A64H * 2) + aoffs, aptr + kn * 32);
            #pragma unroll
            for (int j = 0; j < 2; j++) {
                cpa(uB1 + (unsigned)st * (BSTF * 4) + boffs[j], b1p[j] + kn * 32);
                cpa(uB3 + (unsigned)st * (BSTF * 4) + boffs[j], b3p[j] + kn * 32);
            }
        }
        CP_COMMIT;

        unsigned sAc = uA + (unsigned)(kt % 3) * (A64H * 2);
        const float* B1c = B1b + (kt % 3) * BSTF;
        const float* B3c = B3b + (kt % 3) * BSTF;

        #pragma unroll
        for (int ks = 0; ks < 2; ks++) {
            unsigned af[2][4];
            ldsm4(af[0], sAc + aoffm[0] + ks * 32);
            ldsm4(af[1], sAc + aoffm[1] + ks * 32);
            int k0 = ks * 16 + 2 * bq;
            #pragma unroll
            for (int ni = 0; ni < 2; ni++) {
                int rowb = (wn * 16 + ni * 8 + bn) * SSTF + k0;
                unsigned br1[2], br3[2];
                bfrag(B1c + rowb, br1);
                bfrag(B3c + rowb, br3);
                #pragma unroll
                for (int mi = 0; mi < 2; mi++) {
                    mma16(acc1[mi][ni], af[mi], br1);
                    mma16(acc3[mi][ni], af[mi], br3);
                }
            }
        }
    }

    // epilogue: silu(s1) * s3 -> d_h (fp16)
    #pragma unroll
    for (int mi = 0; mi < 2; mi++)
    #pragma unroll
    for (int ni = 0; ni < 2; ni++)
    #pragma unroll
    for (int h = 0; h < 2; h++) {
        int lr = wm * 32 + mi * 16 + g + h * 8;
        if (m0 + lr < cnt) {
            int col = n0 + wn * 16 + ni * 8 + tg * 2;
            float v1a = acc1[mi][ni][h * 2], v1b = acc1[mi][ni][h * 2 + 1];
            float v3a = acc3[mi][ni][h * 2], v3b = acc3[mi][ni][h * 2 + 1];
            float h0 = v1a * v3a / (1.f + __expf(-v1a));
            float h1 = v1b * v3b / (1.f + __expf(-v1b));
            unsigned u = pk2(h0, h1);
            *(unsigned*)&d_h[((size_t)(e * SLOT + m0 + lr)) * FDIM + col] = u;
        }
    }
}

// ---------------- GEMM2: 128x64 tile, split-K x2, fp16 mma (R5 verbatim) -----
__global__ __launch_bounds__(256, 3) void gemm2_kernel(const float* __restrict__ w2) {
    extern __shared__ __half smh[];
    __half* Ab = smh;                       // 4 * ROWH128
    __half* Bb = smh + 4 * ROWH128;         // 2 * ROWH64

    int e = blockIdx.y >> 2, mtile = blockIdx.y & 3;
    int cnt = d_count[e];
    int m0 = mtile * 128;
    if (m0 >= cnt) return;
    int n0 = blockIdx.x * 64;
    int kz = blockIdx.z;
    int kbase = kz * (FDIM / 2);

    int tid = threadIdx.x;
    const __half* aptr[2]; unsigned aoffs[2];
    #pragma unroll
    for (int j = 0; j < 2; j++) {
        int gidx = tid + 256 * j;
        int row = gidx >> 2, c = gidx & 3;
        int rr = m0 + row; if (rr >= cnt) rr = cnt - 1;
        aptr[j]  = d_h + ((size_t)(e * SLOT) + rr) * FDIM + kbase + c * 8;
        aoffs[j] = (unsigned)(row * SSTH + c * 8) * 2;
    }
    int brow = tid >> 2, bc = tid & 3;
    const float* bp = w2 + ((size_t)e * HDIM + n0 + brow) * FDIM + kbase + bc * 8;
    unsigned bsts = (unsigned)(brow * SSTH + bc * 8) * 2;

    unsigned uA = (unsigned)__cvta_generic_to_shared(Ab);

    const int NKT = (FDIM / 2) / 32;  // 64

    float4 pba = *(const float4*)bp, pbb = *(const float4*)(bp + 4);
    #pragma unroll
    for (int s = 0; s < 3; s++) {
        #pragma unroll
        for (int j = 0; j < 2; j++)
            cpa(uA + (unsigned)s * (ROWH128 * 2) + aoffs[j], aptr[j] + s * 32);
        CP_COMMIT;
    }

    int warp = tid >> 5, lane = tid & 31;
    int wm = warp >> 1, wn = warp & 1;     // 4 x 2 warps, warp tile 32x32
    int g = lane >> 2, tg = lane & 3;

    unsigned aoffm[2], boffp[2];
    #pragma unroll
    for (int mi = 0; mi < 2; mi++)
        aoffm[mi] = (unsigned)((wm * 32 + mi * 16 + (lane & 7) + ((lane >> 3) & 1) * 8) * SSTH
                               + (lane >> 4) * 8) * 2;
    #pragma unroll
    for (int p = 0; p < 2; p++)
        boffp[p] = (unsigned)((wn * 32 + p * 16 + (lane & 7) + ((lane >> 4) & 1) * 8) * SSTH
                              + ((lane >> 3) & 1) * 8) * 2;

    float acc[2][4][4] = {};

    for (int kt = 0; kt < NKT; kt++) {
        { uint4 u; u.x = pk2(pba.x, pba.y); u.y = pk2(pba.z, pba.w);
          u.z = pk2(pbb.x, pbb.y); u.w = pk2(pbb.z, pbb.w);
          *(uint4*)((char*)Bb + ((kt & 1) * (ROWH64 * 2) + bsts)) = u; }
        CP_WAIT2;
        __syncthreads();

        if (kt + 1 < NKT) {
            const float* p = bp + (kt + 1) * 32;
            pba = *(const float4*)p; pbb = *(const float4*)(p + 4);
        }
        if (kt + 3 < NKT) {
            #pragma unroll
            for (int j = 0; j < 2; j++)
                cpa(uA + (unsigned)((kt + 3) & 3) * (ROWH128 * 2) + aoffs[j], aptr[j] + (kt + 3) * 32);
        }
        CP_COMMIT;

        unsigned sAc = uA + (unsigned)(kt & 3) * (ROWH128 * 2);
        unsigned sBc = (unsigned)__cvta_generic_to_shared(Bb) + (unsigned)(kt & 1) * (ROWH64 * 2);

        #pragma unroll
        for (int ks = 0; ks < 2; ks++) {
            unsigned kb = (unsigned)ks * 32;
            unsigned af[2][4], br[2][4];
            ldsm4(af[0], sAc + aoffm[0] + kb);
            ldsm4(af[1], sAc + aoffm[1] + kb);
            ldsm4(br[0], sBc + boffp[0] + kb);
            ldsm4(br[1], sBc + boffp[1] + kb);
            #pragma unroll
            for (int p = 0; p < 2; p++)
            #pragma unroll
            for (int hn = 0; hn < 2; hn++) {
                int ni = p * 2 + hn;
                #pragma unroll
                for (int mi = 0; mi < 2; mi++)
                    mma16(acc[mi][ni], af[mi], &br[p][hn * 2]);
            }
        }
    }

    float* po = d_po2 + (size_t)kz * (NEXP * SLOT * HDIM);
    #pragma unroll
    for (int mi = 0; mi < 2; mi++)
    #pragma unroll
    for (int ni = 0; ni < 4; ni++)
    #pragma unroll
    for (int h = 0; h < 2; h++) {
        int lr = wm * 32 + mi * 16 + g + h * 8;
        if (m0 + lr < cnt) {
            float mult = d_mult[e * SLOT + m0 + lr];
            int col = n0 + wn * 32 + ni * 8 + tg * 2;
            float2 o;
            o.x = acc[mi][ni][h * 2]     * mult;
            o.y = acc[mi][ni][h * 2 + 1] * mult;
            *(float2*)&po[((size_t)(e * SLOT + m0 + lr)) * HDIM + col] = o;
        }
    }
}

// ---------------- finalize (R5 verbatim) -------------------------------------
__global__ void finalize_kernel(float* __restrict__ out) {
    int t = blockIdx.x;
    int i = threadIdx.x;
    int p0 = d_pidx[t * 2], p1 = d_pidx[t * 2 + 1];
    const float* po0 = d_po2;
    const float* po1 = d_po2 + (size_t)(NEXP * SLOT * HDIM);
    float4 a = ((const float4*)(po0 + (size_t)p0 * HDIM))[i];
    float4 b = ((const float4*)(po0 + (size_t)p1 * HDIM))[i];
    float4 c = ((const float4*)(po1 + (size_t)p0 * HDIM))[i];
    float4 d = ((const float4*)(po1 + (size_t)p1 * HDIM))[i];
    float4 o;
    o.x = (a.x + c.x) + (b.x + d.x);
    o.y = (a.y + c.y) + (b.y + d.y);
    o.z = (a.z + c.z) + (b.z + d.z);
    o.w = (a.w + c.w) + (b.w + d.w);
    ((float4*)(out + (size_t)t * HDIM))[i] = o;
}

// ---------------- launch ----------------------------------------------------
extern "C" void kernel_launch(void* const* d_in, const int* in_sizes, int n_in,
                              void* d_out, int out_size) {
    const float* x  = (const float*)d_in[0];
    const float* gw = (const float*)d_in[1];
    const float* w1 = (const float*)d_in[2];
    const float* w2 = (const float*)d_in[3];
    const float* w3 = (const float*)d_in[4];
    float* out = (float*)d_out;

    const int smem1 = 3 * A64H * 2 + 6 * BSTF * 4;       // 70656 B
    const int smem2 = (4 * ROWH128 + 2 * ROWH64) * 2;    // 51200 B
    cudaFuncSetAttribute(gemm1_kernel, cudaFuncAttributeMaxDynamicSharedMemorySize, smem1);
    cudaFuncSetAttribute(gemm2_kernel, cudaFuncAttributeMaxDynamicSharedMemorySize, smem2);

    init_kernel<<<1, 32>>>();
    convx_kernel<<<TOKS * HDIM / 1024, 256>>>(x);
    routing_kernel<<<TOKS, 256>>>(x, gw);
    gemm1_kernel<<<dim3(FDIM / 64, NEXP * 8), 256, smem1>>>(w1, w3);
    gemm2_kernel<<<dim3(HDIM / 64, NEXP * 4, 2), 256, smem2>>>(w2);
    finalize_kernel<<<TOKS, 256>>>(out);
}